// round 8
// baseline (speedup 1.0000x reference)
#include <cuda_runtime.h>
#include <cuda_bf16.h>
#include <mma.h>
#include <math.h>
#include <stdint.h>

// ---------------- Model constants ----------------
#define DEPTH   12
#define DIM     768
#define HEADS   12
#define MLPD    3072
#define PP      16
#define GG      14
#define NCLS    1000
#define NTOK    197
#define HD      64
#define BATCH   32
#define SEQ     (BATCH * NTOK)        // 6304
#define PTOK    196
#define PM      (BATCH * PTOK)        // 6272

// ---------------- Scratch (device globals, no allocations) ----------------
__device__ float g_patches[PM * DIM];
__device__ float g_t     [SEQ * DIM];
__device__ float g_h     [SEQ * DIM];
__device__ float g_qkv   [SEQ * 3 * DIM];
__device__ float g_o     [SEQ * DIM];
__device__ float g_mlp   [SEQ * MLPD];

// tf32-rounded weights, contiguous, SAME layout as the input tensors.
#define WT_PATCH_SZ  (768*768)
#define WT_QKV_SZ    ((long)DEPTH*768*2304)
#define WT_PROJ_SZ   ((long)DEPTH*768*768)
#define WT_FC1_SZ    ((long)DEPTH*768*3072)
#define WT_FC2_SZ    ((long)DEPTH*3072*768)
#define WT_TOTAL     (WT_PATCH_SZ + WT_QKV_SZ + WT_PROJ_SZ + WT_FC1_SZ + WT_FC2_SZ)
__device__ float g_wt[WT_TOTAL];

// ---------------- helpers ----------------
__device__ __forceinline__ float to_tf32(float x) {
    float r;
    asm("cvt.rna.tf32.f32 %0, %1;" : "=f"(r) : "f"(x));
    return r;
}
__device__ __forceinline__ uint32_t smem_u32(const void* p) {
    uint32_t a;
    asm("{ .reg .u64 t; cvta.to.shared.u64 t, %1; cvt.u32.u64 %0, t; }"
        : "=r"(a) : "l"(p));
    return a;
}
__device__ __forceinline__ void cp16(uint32_t dst, const void* src, int srcbytes) {
    asm volatile("cp.async.cg.shared.global [%0], [%1], 16, %2;"
                 :: "r"(dst), "l"(src), "r"(srcbytes) : "memory");
}
#define CP_COMMIT() asm volatile("cp.async.commit_group;" ::: "memory")
#define CP_WAIT(n)  asm volatile("cp.async.wait_group %0;" :: "n"(n) : "memory")

__device__ __forceinline__ float gelu_exact(float x) {
    return 0.5f * x * (1.0f + erff(x * 0.70710678118654752f));
}

// ---------------- weight rounding (fp32 -> tf32-encoded fp32) ----------------
__global__ void round_tf32_kernel(const float* __restrict__ in,
                                  float* __restrict__ out, long n4) {
    long stride = (long)gridDim.x * blockDim.x;
    for (long i = blockIdx.x * (long)blockDim.x + threadIdx.x; i < n4; i += stride) {
        float4 v = ((const float4*)in)[i];
        v.x = to_tf32(v.x); v.y = to_tf32(v.y);
        v.z = to_tf32(v.z); v.w = to_tf32(v.w);
        ((float4*)out)[i] = v;
    }
}

// ---------------- im2col (rounds to tf32: feeds GEMM A) ----------------
__global__ void im2col_kernel(const float* __restrict__ x, float* __restrict__ out) {
    int idx = blockIdx.x * blockDim.x + threadIdx.x;
    if (idx >= PM * DIM) return;
    int row = idx / DIM;
    int col = idx - row * DIM;
    int b  = row / PTOK;
    int pt = row - b * PTOK;
    int gi = pt / GG, gj = pt - gi * GG;
    int c  = col >> 8;
    int r  = col & 255;
    int p1 = r >> 4, p2 = r & 15;
    int xi = ((b * 3 + c) * 224 + gi * PP + p1) * 224 + (gj * PP + p2);
    out[idx] = to_tf32(x[xi]);
}

// ---------------- assemble: cls token + pos embed (residual stream, fp32) ----
__global__ void assemble_kernel(const float* __restrict__ pe,
                                const float* __restrict__ cls,
                                const float* __restrict__ pos,
                                float* __restrict__ t) {
    int idx = blockIdx.x * blockDim.x + threadIdx.x;
    if (idx >= SEQ * DIM) return;
    int row = idx / DIM;
    int c   = idx - row * DIM;
    int b   = row / NTOK;
    int n   = row - b * NTOK;
    float v;
    if (n == 0) v = cls[c];
    else        v = pe[(size_t)(b * PTOK + n - 1) * DIM + c];
    t[idx] = v + pos[n * DIM + c];
}

// ---------------- WMMA tf32 GEMM: C = act(A@W + bias [+res]) ----------------
// A: [M,K] fp32 (tf32-encoded). W: [K,N] fp32 (tf32-encoded). N%128==0, K%32==0.
// Block tile 128x128, K-chunk 32, cp.async double-buffered.
#define BM 128
#define BN 128
#define BK 32
#define AS_STRIDE 36          // floats (pad 4); 144B row, 16B aligned
#define BS_STRIDE 132         // floats (pad 4); 528B row, 16B aligned
#define AS_BYTES (BM * AS_STRIDE * 4)   // 18432
#define BS_BYTES (BK * BS_STRIDE * 4)   // 16896
#define GEMM_SMEM (2 * (AS_BYTES + BS_BYTES))  // 70656

using namespace nvcuda;
typedef wmma::fragment<wmma::matrix_a, 16, 16, 8, wmma::precision::tf32, wmma::row_major> FragA;
typedef wmma::fragment<wmma::matrix_b, 16, 16, 8, wmma::precision::tf32, wmma::row_major> FragB;
typedef wmma::fragment<wmma::accumulator, 16, 16, 8, float> FragC;

__device__ __forceinline__ void gemm_issue_chunk(
    const float* __restrict__ A, const float* __restrict__ W,
    int M, int Nd, int K, int bm0, int bn0, int k0,
    uint32_t aDst, uint32_t bDst, int tid)
{
#pragma unroll
    for (int t = 0; t < 4; t++) {
        int id  = tid + t * 256;           // 0..1023
        int row = id >> 3, c = id & 7;     // A: 8 x float4 per 32-float row
        int gr  = bm0 + row;
        int ok  = (gr < M);
        const float* src = A + (ok ? ((size_t)gr * K + k0 + c * 4) : 0);
        cp16(aDst + row * (AS_STRIDE * 4) + c * 16, src, ok ? 16 : 0);
    }
#pragma unroll
    for (int t = 0; t < 4; t++) {
        int id  = tid + t * 256;
        int row = id >> 5, c = id & 31;    // B: 32 x float4 per 128-float row
        const float* src = W + (size_t)(k0 + row) * Nd + bn0 + c * 4;
        cp16(bDst + row * (BS_STRIDE * 4) + c * 16, src, 16);
    }
    CP_COMMIT();
}

__global__ void __launch_bounds__(256)
gemm_wmma(const float* __restrict__ A, const float* __restrict__ W,
          const float* __restrict__ bias, const float* __restrict__ res,
          float* __restrict__ C, int M, int Nd, int K, int act)
{
    extern __shared__ char sm[];
    uint32_t sbase = smem_u32(sm);
    int tid = threadIdx.x, wid = tid >> 5, lane = tid & 31;
    int bn0 = blockIdx.x * BN, bm0 = blockIdx.y * BM;

    // buffer offsets
    const uint32_t ASO[2] = {0u, (uint32_t)AS_BYTES};
    const uint32_t BSO[2] = {(uint32_t)(2 * AS_BYTES),
                             (uint32_t)(2 * AS_BYTES + BS_BYTES)};

    // warp tiling: 2 (m) x 4 (n); warp tile 64x32
    int wm = (wid & 1) * 64;
    int wn = (wid >> 1) * 32;

    FragC acc[4][2];
#pragma unroll
    for (int i = 0; i < 4; i++)
#pragma unroll
        for (int j = 0; j < 2; j++)
            wmma::fill_fragment(acc[i][j], 0.0f);

    int nc = K / BK;
    gemm_issue_chunk(A, W, M, Nd, K, bm0, bn0, 0, sbase + ASO[0], sbase + BSO[0], tid);

    for (int ci = 0; ci < nc; ci++) {
        int cur = ci & 1;
        if (ci + 1 < nc) {
            int nxt = cur ^ 1;
            gemm_issue_chunk(A, W, M, Nd, K, bm0, bn0, (ci + 1) * BK,
                             sbase + ASO[nxt], sbase + BSO[nxt], tid);
            CP_WAIT(1);
        } else {
            CP_WAIT(0);
        }
        __syncthreads();

        const float* As = (const float*)(sm + ASO[cur]);
        const float* Bs = (const float*)(sm + BSO[cur]);
#pragma unroll
        for (int kk = 0; kk < 4; kk++) {
            FragB bf[2];
#pragma unroll
            for (int j = 0; j < 2; j++)
                wmma::load_matrix_sync(bf[j], Bs + (kk * 8) * BS_STRIDE + wn + j * 16,
                                       BS_STRIDE);
#pragma unroll
            for (int i = 0; i < 4; i++) {
                FragA af;
                wmma::load_matrix_sync(af, As + (wm + i * 16) * AS_STRIDE + kk * 8,
                                       AS_STRIDE);
#pragma unroll
                for (int j = 0; j < 2; j++)
                    wmma::mma_sync(acc[i][j], af, bf[j], acc[i][j]);
            }
        }
        __syncthreads();
    }

    // Epilogue: bounce each 16x16 frag through per-warp smem, apply bias/res/act
    float* patch = (float*)(sm + wid * 1280);   // 16 x 20 floats
    int r  = lane >> 1;
    int cb = (lane & 1) * 8;
#pragma unroll
    for (int i = 0; i < 4; i++) {
#pragma unroll
        for (int j = 0; j < 2; j++) {
            wmma::store_matrix_sync(patch, acc[i][j], 20, wmma::mem_row_major);
            __syncwarp();
            int grow = bm0 + wm + i * 16 + r;
            if (grow < M) {
                int gcol = bn0 + wn + j * 16 + cb;
                float4 v0 = *(const float4*)&patch[r * 20 + cb];
                float4 v1 = *(const float4*)&patch[r * 20 + cb + 4];
                float4 b0 = *(const float4*)&bias[gcol];
                float4 b1 = *(const float4*)&bias[gcol + 4];
                v0.x += b0.x; v0.y += b0.y; v0.z += b0.z; v0.w += b0.w;
                v1.x += b1.x; v1.y += b1.y; v1.z += b1.z; v1.w += b1.w;
                if (res) {
                    float4 r0 = *(const float4*)&res[(size_t)grow * Nd + gcol];
                    float4 r1 = *(const float4*)&res[(size_t)grow * Nd + gcol + 4];
                    v0.x += r0.x; v0.y += r0.y; v0.z += r0.z; v0.w += r0.w;
                    v1.x += r1.x; v1.y += r1.y; v1.z += r1.z; v1.w += r1.w;
                }
                if (act == 1) {
                    v0.x = to_tf32(gelu_exact(v0.x));
                    v0.y = to_tf32(gelu_exact(v0.y));
                    v0.z = to_tf32(gelu_exact(v0.z));
                    v0.w = to_tf32(gelu_exact(v0.w));
                    v1.x = to_tf32(gelu_exact(v1.x));
                    v1.y = to_tf32(gelu_exact(v1.y));
                    v1.z = to_tf32(gelu_exact(v1.z));
                    v1.w = to_tf32(gelu_exact(v1.w));
                }
                *(float4*)&C[(size_t)grow * Nd + gcol]     = v0;
                *(float4*)&C[(size_t)grow * Nd + gcol + 4] = v1;
            }
            __syncwarp();
        }
    }
}

// ---------------- LayerNorm (one block per row, single pass, tf32 output) ----
__global__ void __launch_bounds__(256)
ln_kernel(const float* __restrict__ in, const float* __restrict__ g,
          const float* __restrict__ b, float* __restrict__ out) {
    __shared__ float wsum[8], wsum2[8];
    __shared__ float stats[2];
    int row = blockIdx.x, tid = threadIdx.x, wid = tid >> 5, lane = tid & 31;
    const float* x = in + (size_t)row * DIM;
    float v0 = x[tid], v1 = x[tid + 256], v2 = x[tid + 512];
    float s  = v0 + v1 + v2;
    float s2 = v0 * v0 + v1 * v1 + v2 * v2;
#pragma unroll
    for (int off = 16; off > 0; off >>= 1) {
        s  += __shfl_xor_sync(0xffffffffu, s,  off);
        s2 += __shfl_xor_sync(0xffffffffu, s2, off);
    }
    if (lane == 0) { wsum[wid] = s; wsum2[wid] = s2; }
    __syncthreads();
    if (tid == 0) {
        float a = 0.f, c = 0.f;
#pragma unroll
        for (int i = 0; i < 8; i++) { a += wsum[i]; c += wsum2[i]; }
        float m = a * (1.0f / DIM);
        stats[0] = m;
        stats[1] = rsqrtf(c * (1.0f / DIM) - m * m + 1e-6f);
    }
    __syncthreads();
    float m = stats[0], rs = stats[1];
    float* y = out + (size_t)row * DIM;
    y[tid]       = to_tf32((v0 - m) * rs * g[tid]       + b[tid]);
    y[tid + 256] = to_tf32((v1 - m) * rs * g[tid + 256] + b[tid + 256]);
    y[tid + 512] = to_tf32((v2 - m) * rs * g[tid + 512] + b[tid + 512]);
}

// ---------------- Attention (one block per (b, head)) ----------------
#define KSTRIDE 65
#define SM_K    0
#define SM_V    12808
#define SM_Q    (SM_V + 197 * 64)
#define SM_P    (SM_Q + 8 * 64)
#define SM_ATTN_FLOATS (SM_P + 8 * 200)
#define SM_ATTN_BYTES  (SM_ATTN_FLOATS * 4)

__global__ void __launch_bounds__(256)
attn_kernel(const float* __restrict__ qkv, const float* __restrict__ mask,
            float* __restrict__ o) {
    extern __shared__ float smf[];
    float* Ksm = smf + SM_K;
    float* Vsm = smf + SM_V;
    int h = blockIdx.x;
    int b = blockIdx.y;
    int tid = threadIdx.x;
    const float* base = qkv + (size_t)b * NTOK * (3 * DIM);

    for (int i4 = tid; i4 < NTOK * 16; i4 += 256) {
        int n  = i4 >> 4;
        int d4 = (i4 & 15) << 2;
        const float* rowp = base + (size_t)n * (3 * DIM) + h * HD + d4;
        float4 kv = *(const float4*)(rowp + DIM);
        Ksm[n * KSTRIDE + d4 + 0] = kv.x;
        Ksm[n * KSTRIDE + d4 + 1] = kv.y;
        Ksm[n * KSTRIDE + d4 + 2] = kv.z;
        Ksm[n * KSTRIDE + d4 + 3] = kv.w;
        *(float4*)&Vsm[n * 64 + d4] = *(const float4*)(rowp + 2 * DIM);
    }
    __syncthreads();

    int wid = tid >> 5, lane = tid & 31;
    float* q = smf + SM_Q + wid * 64;
    float* p = smf + SM_P + wid * 200;

    for (int qi = wid; qi < NTOK; qi += 8) {
        const float* qrow = base + (size_t)qi * (3 * DIM) + h * HD;
        q[lane]      = qrow[lane];
        q[lane + 32] = qrow[lane + 32];
        __syncwarp();

        float s[7];
        float mx = -1e30f;
#pragma unroll
        for (int t = 0; t < 7; t++) {
            int j = t * 32 + lane;
            if (j < NTOK) {
                float acc = 0.0f;
#pragma unroll
                for (int d = 0; d < HD; d++)
                    acc = fmaf(q[d], Ksm[j * KSTRIDE + d], acc);
                acc *= 0.125f;
                acc *= mask[qi * NTOK + j];
                s[t] = acc;
                mx = fmaxf(mx, acc);
            } else {
                s[t] = -1e30f;
            }
        }
#pragma unroll
        for (int off = 16; off > 0; off >>= 1)
            mx = fmaxf(mx, __shfl_xor_sync(0xffffffffu, mx, off));

        float sum = 0.0f;
#pragma unroll
        for (int t = 0; t < 7; t++) {
            s[t] = __expf(s[t] - mx);
            sum += s[t];
        }
#pragma unroll
        for (int off = 16; off > 0; off >>= 1)
            sum += __shfl_xor_sync(0xffffffffu, sum, off);
        float inv = 1.0f / sum;
#pragma unroll
        for (int t = 0; t < 7; t++) {
            int j = t * 32 + lane;
            if (j < NTOK) p[j] = s[t] * inv;
        }
        __syncwarp();

        float* op = o + (size_t)(b * NTOK + qi) * DIM + h * HD;
#pragma unroll
        for (int dd = 0; dd < 2; dd++) {
            int d = lane + dd * 32;
            float acc = 0.0f;
            for (int j = 0; j < NTOK; j++)
                acc = fmaf(p[j], Vsm[j * 64 + d], acc);
            op[d] = to_tf32(acc);   // feeds proj GEMM A operand
        }
        __syncwarp();
    }
}

// ---------------- Head ----------------
__global__ void __launch_bounds__(256)
head_kernel(const float* __restrict__ hf, const float* __restrict__ w,
            const float* __restrict__ hb, float* __restrict__ out) {
    __shared__ float pooled[DIM];
    int b = blockIdx.x;
    int tid = threadIdx.x;
    for (int i = tid; i < DIM; i += 256)
        pooled[i] = hf[(size_t)(b * NTOK) * DIM + i];
    __syncthreads();
    for (int c = tid; c < NCLS; c += 256) {
        float acc = hb[c];
        for (int d = 0; d < DIM; d++)
            acc = fmaf(pooled[d], w[(size_t)d * NCLS + c], acc);
        out[(size_t)b * NCLS + c] = acc;
    }
}

// ---------------- Launch ----------------
extern "C" void kernel_launch(void* const* d_in, const int* in_sizes, int n_in,
                              void* d_out, int out_size) {
    const float* x        = (const float*)d_in[0];
    const float* cp_mask  = (const float*)d_in[1];
    const float* patch_w  = (const float*)d_in[2];
    const float* patch_b  = (const float*)d_in[3];
    const float* cls_tok  = (const float*)d_in[4];
    const float* pos_emb  = (const float*)d_in[5];
    const float* ln1_g    = (const float*)d_in[6];
    const float* ln1_b    = (const float*)d_in[7];
    const float* qkv_w    = (const float*)d_in[8];
    const float* qkv_b    = (const float*)d_in[9];
    const float* proj_w   = (const float*)d_in[10];
    const float* proj_b   = (const float*)d_in[11];
    const float* ln2_g    = (const float*)d_in[12];
    const float* ln2_b    = (const float*)d_in[13];
    const float* fc1_w    = (const float*)d_in[14];
    const float* fc1_b    = (const float*)d_in[15];
    const float* fc2_w    = (const float*)d_in[16];
    const float* fc2_b    = (const float*)d_in[17];
    const float* normf_g  = (const float*)d_in[18];
    const float* normf_b  = (const float*)d_in[19];
    const float* head_w   = (const float*)d_in[20];
    const float* head_b   = (const float*)d_in[21];
    float* out = (float*)d_out;

    float *pat, *t, *h, *qkv, *o, *mlp, *wt;
    cudaGetSymbolAddress((void**)&pat, g_patches);
    cudaGetSymbolAddress((void**)&t,   g_t);
    cudaGetSymbolAddress((void**)&h,   g_h);
    cudaGetSymbolAddress((void**)&qkv, g_qkv);
    cudaGetSymbolAddress((void**)&o,   g_o);
    cudaGetSymbolAddress((void**)&mlp, g_mlp);
    cudaGetSymbolAddress((void**)&wt,  g_wt);

    cudaFuncSetAttribute(attn_kernel,
                         cudaFuncAttributeMaxDynamicSharedMemorySize, SM_ATTN_BYTES);
    cudaFuncSetAttribute(gemm_wmma,
                         cudaFuncAttributeMaxDynamicSharedMemorySize, GEMM_SMEM);

    // Contiguous tf32 copies, same layout as inputs.
    float* wt_patch = wt;
    float* wt_qkv   = wt_patch + WT_PATCH_SZ;
    float* wt_proj  = wt_qkv   + WT_QKV_SZ;
    float* wt_fc1   = wt_proj  + WT_PROJ_SZ;
    float* wt_fc2   = wt_fc1   + WT_FC1_SZ;

    // ---- round weights to tf32 (5 whole-blob launches) ----
    round_tf32_kernel<<<512, 256>>>(patch_w, wt_patch, (long)WT_PATCH_SZ / 4);
    round_tf32_kernel<<<1024, 256>>>(qkv_w,  wt_qkv,  WT_QKV_SZ  / 4);
    round_tf32_kernel<<<1024, 256>>>(proj_w, wt_proj, WT_PROJ_SZ / 4);
    round_tf32_kernel<<<1024, 256>>>(fc1_w,  wt_fc1,  WT_FC1_SZ  / 4);
    round_tf32_kernel<<<1024, 256>>>(fc2_w,  wt_fc2,  WT_FC2_SZ  / 4);

    // ---- forward ----
    {
        int total = PM * DIM;
        im2col_kernel<<<(total + 255) / 256, 256>>>(x, pat);
    }
    {   // patch embed: (6272,768)@(768,768)
        dim3 grid(768 / 128, PM / 128);
        gemm_wmma<<<grid, 256, GEMM_SMEM>>>(pat, wt_patch, patch_b, nullptr, o,
                                            PM, 768, 768, 0);
    }
    {
        int total = SEQ * DIM;
        assemble_kernel<<<(total + 255) / 256, 256>>>(o, cls_tok, pos_emb, t);
    }

    for (int i = 0; i < DEPTH; i++) {
        ln_kernel<<<SEQ, 256>>>(t, ln1_g + i * DIM, ln1_b + i * DIM, h);
        {   // QKV: (6304,768)@(768,2304)
            dim3 grid((3 * DIM) / 128, (SEQ + 127) / 128);
            gemm_wmma<<<grid, 256, GEMM_SMEM>>>(h, wt_qkv + (size_t)i * 768 * 2304,
                                                qkv_b + i * 3 * DIM, nullptr, qkv,
                                                SEQ, 3 * DIM, DIM, 0);
        }
        {
            dim3 grid(HEADS, BATCH);
            attn_kernel<<<grid, 256, SM_ATTN_BYTES>>>(qkv, cp_mask, o);
        }
        {   // proj + residual: t = t + o @ proj_w + proj_b
            dim3 grid(DIM / 128, (SEQ + 127) / 128);
            gemm_wmma<<<grid, 256, GEMM_SMEM>>>(o, wt_proj + (size_t)i * 768 * 768,
                                                proj_b + i * DIM, t, t,
                                                SEQ, DIM, DIM, 0);
        }
        ln_kernel<<<SEQ, 256>>>(t, ln2_g + i * DIM, ln2_b + i * DIM, h);
        {   // fc1 + GELU: (6304,768)@(768,3072)
            dim3 grid(MLPD / 128, (SEQ + 127) / 128);
            gemm_wmma<<<grid, 256, GEMM_SMEM>>>(h, wt_fc1 + (size_t)i * 768 * 3072,
                                                fc1_b + i * MLPD, nullptr, mlp,
                                                SEQ, MLPD, DIM, 1);
        }
        {   // fc2 + residual: t = t + mlp @ fc2_w + fc2_b
            dim3 grid(DIM / 128, (SEQ + 127) / 128);
            gemm_wmma<<<grid, 256, GEMM_SMEM>>>(mlp, wt_fc2 + (size_t)i * 3072 * 768,
                                                fc2_b + i * DIM, t, t,
                                                SEQ, DIM, MLPD, 0);
        }
    }

    ln_kernel<<<SEQ, 256>>>(t, normf_g, normf_b, h);
    head_kernel<<<BATCH, 256>>>(h, head_w, head_b, out);
}

// round 10
// speedup vs baseline: 3.4005x; 3.4005x over previous
#include <cuda_runtime.h>
#include <cuda_fp16.h>
#include <mma.h>
#include <math.h>
#include <stdint.h>

// ---------------- Model constants ----------------
#define DEPTH   12
#define DIM     768
#define HEADS   12
#define MLPD    3072
#define PP      16
#define GG      14
#define NCLS    1000
#define NTOK    197
#define HD      64
#define BATCH   32
#define SEQ     (BATCH * NTOK)        // 6304
#define PTOK    196
#define PM      (BATCH * PTOK)        // 6272

// ---------------- Scratch (device globals, no allocations) ----------------
__device__ __half g_patches[PM * DIM];        // im2col out (fp16)
__device__ float  g_t      [SEQ * DIM];       // residual stream (fp32)
__device__ __half g_h      [SEQ * DIM];       // LN out (fp16)
__device__ __half g_qkv    [SEQ * 3 * DIM];   // qkv (fp16)
__device__ __half g_o      [SEQ * DIM];       // attn out (fp16)
__device__ __half g_mlp    [SEQ * MLPD];      // MLP hidden (fp16); also reused
                                              // as fp32 temp for patch-embed out

// fp16 weights, contiguous, same layout as inputs.
#define WT_PATCH_SZ  ((long)768*768)
#define WT_QKV_SZ    ((long)DEPTH*768*2304)
#define WT_PROJ_SZ   ((long)DEPTH*768*768)
#define WT_FC1_SZ    ((long)DEPTH*768*3072)
#define WT_FC2_SZ    ((long)DEPTH*3072*768)
#define WT_TOTAL     (WT_PATCH_SZ + WT_QKV_SZ + WT_PROJ_SZ + WT_FC1_SZ + WT_FC2_SZ)
__device__ __half g_wt[WT_TOTAL];

// ---------------- helpers ----------------
__device__ __forceinline__ uint32_t smem_u32(const void* p) {
    uint32_t a;
    asm("{ .reg .u64 t; cvta.to.shared.u64 t, %1; cvt.u32.u64 %0, t; }"
        : "=r"(a) : "l"(p));
    return a;
}
__device__ __forceinline__ void cp16(uint32_t dst, const void* src, int srcbytes) {
    asm volatile("cp.async.cg.shared.global [%0], [%1], 16, %2;"
                 :: "r"(dst), "l"(src), "r"(srcbytes) : "memory");
}
#define CP_COMMIT() asm volatile("cp.async.commit_group;" ::: "memory")
#define CP_WAIT(n)  asm volatile("cp.async.wait_group %0;" :: "n"(n) : "memory")

__device__ __forceinline__ float gelu_exact(float x) {
    return 0.5f * x * (1.0f + erff(x * 0.70710678118654752f));
}

// ---------------- weight conversion fp32 -> fp16 ----------------
__global__ void round_half_kernel(const float* __restrict__ in,
                                  __half* __restrict__ out, long n4) {
    long stride = (long)gridDim.x * blockDim.x;
    for (long i = blockIdx.x * (long)blockDim.x + threadIdx.x; i < n4; i += stride) {
        float4 v = ((const float4*)in)[i];
        ((__half2*)out)[2 * i]     = __floats2half2_rn(v.x, v.y);
        ((__half2*)out)[2 * i + 1] = __floats2half2_rn(v.z, v.w);
    }
}

// ---------------- im2col -> fp16 ----------------
__global__ void im2col_kernel(const float* __restrict__ x, __half* __restrict__ out) {
    int idx = blockIdx.x * blockDim.x + threadIdx.x;
    if (idx >= PM * DIM) return;
    int row = idx / DIM;
    int col = idx - row * DIM;
    int b  = row / PTOK;
    int pt = row - b * PTOK;
    int gi = pt / GG, gj = pt - gi * GG;
    int c  = col >> 8;
    int r  = col & 255;
    int p1 = r >> 4, p2 = r & 15;
    int xi = ((b * 3 + c) * 224 + gi * PP + p1) * 224 + (gj * PP + p2);
    out[idx] = __float2half(x[xi]);
}

// ---------------- assemble: cls + pos (fp32 residual stream) ----------------
__global__ void assemble_kernel(const float* __restrict__ pe,
                                const float* __restrict__ cls,
                                const float* __restrict__ pos,
                                float* __restrict__ t) {
    int idx = blockIdx.x * blockDim.x + threadIdx.x;
    if (idx >= SEQ * DIM) return;
    int row = idx / DIM;
    int c   = idx - row * DIM;
    int b   = row / NTOK;
    int n   = row - b * NTOK;
    float v;
    if (n == 0) v = cls[c];
    else        v = pe[(size_t)(b * PTOK + n - 1) * DIM + c];
    t[idx] = v + pos[n * DIM + c];
}

// ---------------- fp16 WMMA GEMM: C = act(A@W + bias [+res]) ----------------
// A: [M,K] half. W: [K,N] half. N%128==0, K%32==0.
// flags: bit0 = GELU, bit1 = output is __half (else float).
#define BM 128
#define BN 128
#define BK 32
#define AS_H 40            // halves per A smem row (32 + 8 pad); 80 B
#define BS_H 136           // halves per B smem row (128 + 8 pad); 272 B
#define A_TILE_B (BM * AS_H * 2)   // 10240
#define B_TILE_B (BK * BS_H * 2)   // 8704
#define GEMM_SMEM (2 * (A_TILE_B + B_TILE_B))  // 37888

using namespace nvcuda;
typedef wmma::fragment<wmma::matrix_a, 16, 16, 16, __half, wmma::row_major> FragA;
typedef wmma::fragment<wmma::matrix_b, 16, 16, 16, __half, wmma::row_major> FragB;
typedef wmma::fragment<wmma::accumulator, 16, 16, 16, float> FragC;

__device__ __forceinline__ void gemm_issue_chunk_h(
    const __half* __restrict__ A, const __half* __restrict__ W,
    int M, int Nd, int K, int bm0, int bn0, int k0,
    uint32_t aDst, uint32_t bDst, int tid)
{
#pragma unroll
    for (int t = 0; t < 2; t++) {                // A: 128 rows x 4 chunks
        int id  = tid + t * 256;
        int row = id >> 2, c = id & 3;
        int gr  = bm0 + row;
        int ok  = (gr < M);
        const __half* src = A + (ok ? ((size_t)gr * K + k0 + c * 8) : 0);
        cp16(aDst + row * (AS_H * 2) + c * 16, src, ok ? 16 : 0);
    }
#pragma unroll
    for (int t = 0; t < 2; t++) {                // B: 32 rows x 16 chunks
        int id  = tid + t * 256;
        int row = id >> 4, c = id & 15;
        const __half* src = W + (size_t)(k0 + row) * Nd + bn0 + c * 8;
        cp16(bDst + row * (BS_H * 2) + c * 16, src, 16);
    }
    CP_COMMIT();
}

__global__ void __launch_bounds__(256)
gemm_wmma_h(const __half* __restrict__ A, const __half* __restrict__ W,
            const float* __restrict__ bias, const float* __restrict__ res,
            void* __restrict__ Cv, int M, int Nd, int K, int flags)
{
    extern __shared__ char sm[];
    uint32_t sbase = smem_u32(sm);
    int tid = threadIdx.x, wid = tid >> 5, lane = tid & 31;
    int bn0 = blockIdx.x * BN, bm0 = blockIdx.y * BM;

    const uint32_t ASO[2] = {0u, (uint32_t)A_TILE_B};
    const uint32_t BSO[2] = {(uint32_t)(2 * A_TILE_B),
                             (uint32_t)(2 * A_TILE_B + B_TILE_B)};

    // warp tiling: 2 (m) x 4 (n); warp tile 64x32
    int wm = (wid & 1) * 64;
    int wn = (wid >> 1) * 32;

    FragC acc[4][2];
#pragma unroll
    for (int i = 0; i < 4; i++)
#pragma unroll
        for (int j = 0; j < 2; j++)
            wmma::fill_fragment(acc[i][j], 0.0f);

    int nc = K / BK;
    gemm_issue_chunk_h(A, W, M, Nd, K, bm0, bn0, 0,
                       sbase + ASO[0], sbase + BSO[0], tid);

    for (int ci = 0; ci < nc; ci++) {
        int cur = ci & 1;
        if (ci + 1 < nc) {
            int nxt = cur ^ 1;
            gemm_issue_chunk_h(A, W, M, Nd, K, bm0, bn0, (ci + 1) * BK,
                               sbase + ASO[nxt], sbase + BSO[nxt], tid);
            CP_WAIT(1);
        } else {
            CP_WAIT(0);
        }
        __syncthreads();

        const __half* As = (const __half*)(sm + ASO[cur]);
        const __half* Bs = (const __half*)(sm + BSO[cur]);
#pragma unroll
        for (int kk = 0; kk < 2; kk++) {
            FragB bf[2];
#pragma unroll
            for (int j = 0; j < 2; j++)
                wmma::load_matrix_sync(bf[j], Bs + (kk * 16) * BS_H + wn + j * 16,
                                       BS_H);
#pragma unroll
            for (int i = 0; i < 4; i++) {
                FragA af;
                wmma::load_matrix_sync(af, As + (wm + i * 16) * AS_H + kk * 16,
                                       AS_H);
#pragma unroll
                for (int j = 0; j < 2; j++)
                    wmma::mma_sync(acc[i][j], af, bf[j], acc[i][j]);
            }
        }
        __syncthreads();
    }

    // Epilogue: bounce each 16x16 frag through per-warp smem
    float* patch = (float*)(sm + wid * 1280);   // 16 x 20 floats
    int r  = lane >> 1;
    int cb = (lane & 1) * 8;
    int doGelu  = flags & 1;
    int outHalf = flags & 2;
#pragma unroll
    for (int i = 0; i < 4; i++) {
#pragma unroll
        for (int j = 0; j < 2; j++) {
            wmma::store_matrix_sync(patch, acc[i][j], 20, wmma::mem_row_major);
            __syncwarp();
            int grow = bm0 + wm + i * 16 + r;
            if (grow < M) {
                int gcol = bn0 + wn + j * 16 + cb;
                float4 v0 = *(const float4*)&patch[r * 20 + cb];
                float4 v1 = *(const float4*)&patch[r * 20 + cb + 4];
                float4 b0 = *(const float4*)&bias[gcol];
                float4 b1 = *(const float4*)&bias[gcol + 4];
                v0.x += b0.x; v0.y += b0.y; v0.z += b0.z; v0.w += b0.w;
                v1.x += b1.x; v1.y += b1.y; v1.z += b1.z; v1.w += b1.w;
                if (res) {
                    float4 r0 = *(const float4*)&res[(size_t)grow * Nd + gcol];
                    float4 r1 = *(const float4*)&res[(size_t)grow * Nd + gcol + 4];
                    v0.x += r0.x; v0.y += r0.y; v0.z += r0.z; v0.w += r0.w;
                    v1.x += r1.x; v1.y += r1.y; v1.z += r1.z; v1.w += r1.w;
                }
                if (doGelu) {
                    v0.x = gelu_exact(v0.x); v0.y = gelu_exact(v0.y);
                    v0.z = gelu_exact(v0.z); v0.w = gelu_exact(v0.w);
                    v1.x = gelu_exact(v1.x); v1.y = gelu_exact(v1.y);
                    v1.z = gelu_exact(v1.z); v1.w = gelu_exact(v1.w);
                }
                if (outHalf) {
                    union { uint4 u; __half2 h[4]; } pk;
                    pk.h[0] = __floats2half2_rn(v0.x, v0.y);
                    pk.h[1] = __floats2half2_rn(v0.z, v0.w);
                    pk.h[2] = __floats2half2_rn(v1.x, v1.y);
                    pk.h[3] = __floats2half2_rn(v1.z, v1.w);
                    *(uint4*)&((__half*)Cv)[(size_t)grow * Nd + gcol] = pk.u;
                } else {
                    float* C = (float*)Cv;
                    *(float4*)&C[(size_t)grow * Nd + gcol]     = v0;
                    *(float4*)&C[(size_t)grow * Nd + gcol + 4] = v1;
                }
            }
            __syncwarp();
        }
    }
}

// ---------------- LayerNorm: fp32 in, fp16 out ----------------
__global__ void __launch_bounds__(256)
ln_kernel(const float* __restrict__ in, const float* __restrict__ g,
          const float* __restrict__ b, __half* __restrict__ out) {
    __shared__ float wsum[8], wsum2[8];
    __shared__ float stats[2];
    int row = blockIdx.x, tid = threadIdx.x, wid = tid >> 5, lane = tid & 31;
    const float* x = in + (size_t)row * DIM;
    float v0 = x[tid], v1 = x[tid + 256], v2 = x[tid + 512];
    float s  = v0 + v1 + v2;
    float s2 = v0 * v0 + v1 * v1 + v2 * v2;
#pragma unroll
    for (int off = 16; off > 0; off >>= 1) {
        s  += __shfl_xor_sync(0xffffffffu, s,  off);
        s2 += __shfl_xor_sync(0xffffffffu, s2, off);
    }
    if (lane == 0) { wsum[wid] = s; wsum2[wid] = s2; }
    __syncthreads();
    if (tid == 0) {
        float a = 0.f, c = 0.f;
#pragma unroll
        for (int i = 0; i < 8; i++) { a += wsum[i]; c += wsum2[i]; }
        float m = a * (1.0f / DIM);
        stats[0] = m;
        stats[1] = rsqrtf(c * (1.0f / DIM) - m * m + 1e-6f);
    }
    __syncthreads();
    float m = stats[0], rs = stats[1];
    __half* y = out + (size_t)row * DIM;
    y[tid]       = __float2half((v0 - m) * rs * g[tid]       + b[tid]);
    y[tid + 256] = __float2half((v1 - m) * rs * g[tid + 256] + b[tid + 256]);
    y[tid + 512] = __float2half((v2 - m) * rs * g[tid + 512] + b[tid + 512]);
}

// ---------------- Attention (one block per (b, head)); qkv fp16 ----------------
#define KSTRIDE 65
#define SM_K    0
#define SM_V    12808
#define SM_Q    (SM_V + 197 * 64)
#define SM_P    (SM_Q + 8 * 64)
#define SM_ATTN_FLOATS (SM_P + 8 * 200)
#define SM_ATTN_BYTES  (SM_ATTN_FLOATS * 4)

__global__ void __launch_bounds__(256)
attn_kernel(const __half* __restrict__ qkv, const float* __restrict__ mask,
            __half* __restrict__ o) {
    extern __shared__ float smf[];
    float* Ksm = smf + SM_K;
    float* Vsm = smf + SM_V;
    int h = blockIdx.x;
    int b = blockIdx.y;
    int tid = threadIdx.x;
    const __half* base = qkv + (size_t)b * NTOK * (3 * DIM);

    // stage K, V (fp16 -> fp32 smem)
    for (int idx = tid; idx < NTOK * 32; idx += 256) {
        int n  = idx >> 5;
        int d2 = idx & 31;                   // half2 index within 64 dims
        const __half* rowp = base + (size_t)n * (3 * DIM) + h * HD;
        __half2 kv = ((const __half2*)(rowp + DIM))[d2];
        __half2 vv = ((const __half2*)(rowp + 2 * DIM))[d2];
        float2 kf = __half22float2(kv);
        float2 vf = __half22float2(vv);
        Ksm[n * KSTRIDE + 2 * d2]     = kf.x;
        Ksm[n * KSTRIDE + 2 * d2 + 1] = kf.y;
        Vsm[n * 64 + 2 * d2]     = vf.x;
        Vsm[n * 64 + 2 * d2 + 1] = vf.y;
    }
    __syncthreads();

    int wid = tid >> 5, lane = tid & 31;
    float* q = smf + SM_Q + wid * 64;
    float* p = smf + SM_P + wid * 200;

    for (int qi = wid; qi < NTOK; qi += 8) {
        const __half* qrow = base + (size_t)qi * (3 * DIM) + h * HD;
        q[lane]      = __half2float(qrow[lane]);
        q[lane + 32] = __half2float(qrow[lane + 32]);
        __syncwarp();

        float s[7];
        float mx = -1e30f;
#pragma unroll
        for (int t = 0; t < 7; t++) {
            int j = t * 32 + lane;
            if (j < NTOK) {
                float acc = 0.0f;
#pragma unroll
                for (int d = 0; d < HD; d++)
                    acc = fmaf(q[d], Ksm[j * KSTRIDE + d], acc);
                acc *= 0.125f;
                acc *= mask[qi * NTOK + j];
                s[t] = acc;
                mx = fmaxf(mx, acc);
            } else {
                s[t] = -1e30f;
            }
        }
#pragma unroll
        for (int off = 16; off > 0; off >>= 1)
            mx = fmaxf(mx, __shfl_xor_sync(0xffffffffu, mx, off));

        float sum = 0.0f;
#pragma unroll
        for (int t = 0; t < 7; t++) {
            s[t] = __expf(s[t] - mx);
            sum += s[t];
        }
#pragma unroll
        for (int off = 16; off > 0; off >>= 1)
            sum += __shfl_xor_sync(0xffffffffu, sum, off);
        float inv = 1.0f / sum;
#pragma unroll
        for (int t = 0; t < 7; t++) {
            int j = t * 32 + lane;
            if (j < NTOK) p[j] = s[t] * inv;
        }
        __syncwarp();

        __half* op = o + (size_t)(b * NTOK + qi) * DIM + h * HD;
#pragma unroll
        for (int dd = 0; dd < 2; dd++) {
            int d = lane + dd * 32;
            float acc = 0.0f;
            for (int j = 0; j < NTOK; j++)
                acc = fmaf(p[j], Vsm[j * 64 + d], acc);
            op[d] = __float2half(acc);
        }
        __syncwarp();
    }
}

// ---------------- Head: pooled (fp16 in, fp32 math) ----------------
__global__ void __launch_bounds__(256)
head_kernel(const __half* __restrict__ hf, const float* __restrict__ w,
            const float* __restrict__ hb, float* __restrict__ out) {
    __shared__ float pooled[DIM];
    int b = blockIdx.x;
    int tid = threadIdx.x;
    for (int i = tid; i < DIM; i += 256)
        pooled[i] = __half2float(hf[(size_t)(b * NTOK) * DIM + i]);
    __syncthreads();
    for (int c = tid; c < NCLS; c += 256) {
        float acc = hb[c];
        for (int d = 0; d < DIM; d++)
            acc = fmaf(pooled[d], w[(size_t)d * NCLS + c], acc);
        out[(size_t)b * NCLS + c] = acc;
    }
}

// ---------------- Launch ----------------
extern "C" void kernel_launch(void* const* d_in, const int* in_sizes, int n_in,
                              void* d_out, int out_size) {
    const float* x        = (const float*)d_in[0];
    const float* cp_mask  = (const float*)d_in[1];
    const float* patch_w  = (const float*)d_in[2];
    const float* patch_b  = (const float*)d_in[3];
    const float* cls_tok  = (const float*)d_in[4];
    const float* pos_emb  = (const float*)d_in[5];
    const float* ln1_g    = (const float*)d_in[6];
    const float* ln1_b    = (const float*)d_in[7];
    const float* qkv_w    = (const float*)d_in[8];
    const float* qkv_b    = (const float*)d_in[9];
    const float* proj_w   = (const float*)d_in[10];
    const float* proj_b   = (const float*)d_in[11];
    const float* ln2_g    = (const float*)d_in[12];
    const float* ln2_b    = (const float*)d_in[13];
    const float* fc1_w    = (const float*)d_in[14];
    const float* fc1_b    = (const float*)d_in[15];
    const float* fc2_w    = (const float*)d_in[16];
    const float* fc2_b    = (const float*)d_in[17];
    const float* normf_g  = (const float*)d_in[18];
    const float* normf_b  = (const float*)d_in[19];
    const float* head_w   = (const float*)d_in[20];
    const float* head_b   = (const float*)d_in[21];
    float* out = (float*)d_out;

    __half *pat, *h, *qkv, *o, *mlp, *wt;
    float *t;
    cudaGetSymbolAddress((void**)&pat, g_patches);
    cudaGetSymbolAddress((void**)&t,   g_t);
    cudaGetSymbolAddress((void**)&h,   g_h);
    cudaGetSymbolAddress((void**)&qkv, g_qkv);
    cudaGetSymbolAddress((void**)&o,   g_o);
    cudaGetSymbolAddress((void**)&mlp, g_mlp);
    cudaGetSymbolAddress((void**)&wt,  g_wt);

    cudaFuncSetAttribute(attn_kernel,
                         cudaFuncAttributeMaxDynamicSharedMemorySize, SM_ATTN_BYTES);
    cudaFuncSetAttribute(gemm_wmma_h,
                         cudaFuncAttributeMaxDynamicSharedMemorySize, GEMM_SMEM);

    __half* wt_patch = wt;
    __half* wt_qkv   = wt_patch + WT_PATCH_SZ;
    __half* wt_proj  = wt_qkv   + WT_QKV_SZ;
    __half* wt_fc1   = wt_proj  + WT_PROJ_SZ;
    __half* wt_fc2   = wt_fc1   + WT_FC1_SZ;

    // patch-embed fp32 temp lives in g_mlp's storage (consumed by assemble
    // before fc1 ever writes g_mlp)
    float* patch_out = (float*)mlp;

    // Launch order puts the patch-embed GEMM in ncu's capture slot (-s 5 -c 1).
    {   // 1: im2col
        int total = PM * DIM;
        im2col_kernel<<<(total + 255) / 256, 256>>>(x, pat);
    }
    // 2-4: weight conversions needed before the first GEMM
    round_half_kernel<<<512, 256>>>(patch_w, wt_patch, WT_PATCH_SZ / 4);
    round_half_kernel<<<1024, 256>>>(qkv_w,  wt_qkv,  WT_QKV_SZ  / 4);
    round_half_kernel<<<1024, 256>>>(proj_w, wt_proj, WT_PROJ_SZ / 4);
    {   // 5: patch embed GEMM (profiled): (6272,768)@(768,768) -> fp32 temp
        dim3 grid(768 / 128, PM / 128);
        gemm_wmma_h<<<grid, 256, GEMM_SMEM>>>(pat, wt_patch, patch_b, nullptr,
                                              patch_out, PM, 768, 768, 0);
    }
    round_half_kernel<<<1024, 256>>>(fc1_w, wt_fc1, WT_FC1_SZ / 4);
    round_half_kernel<<<1024, 256>>>(fc2_w, wt_fc2, WT_FC2_SZ / 4);
    {   // assemble cls + pos -> t (fp32)
        int total = SEQ * DIM;
        assemble_kernel<<<(total + 255) / 256, 256>>>(patch_out, cls_tok, pos_emb, t);
    }

    for (int i = 0; i < DEPTH; i++) {
        ln_kernel<<<SEQ, 256>>>(t, ln1_g + i * DIM, ln1_b + i * DIM, h);
        {   // QKV: (6304,768)@(768,2304) -> fp16
            dim3 grid((3 * DIM) / 128, (SEQ + 127) / 128);
            gemm_wmma_h<<<grid, 256, GEMM_SMEM>>>(h, wt_qkv + (size_t)i * 768 * 2304,
                                                  qkv_b + i * 3 * DIM, nullptr, qkv,
                                                  SEQ, 3 * DIM, DIM, 2);
        }
        {
            dim3 grid(HEADS, BATCH);
            attn_kernel<<<grid, 256, SM_ATTN_BYTES>>>(qkv, cp_mask, o);
        }
        {   // proj + residual -> t (fp32)
            dim3 grid(DIM / 128, (SEQ + 127) / 128);
            gemm_wmma_h<<<grid, 256, GEMM_SMEM>>>(o, wt_proj + (size_t)i * 768 * 768,
                                                  proj_b + i * DIM, t, t,
                                                  SEQ, DIM, DIM, 0);
        }
        ln_kernel<<<SEQ, 256>>>(t, ln2_g + i * DIM, ln2_b + i * DIM, h);
        {   // fc1 + GELU -> fp16
            dim3 grid(MLPD / 128, (SEQ + 127) / 128);
            gemm_wmma_h<<<grid, 256, GEMM_SMEM>>>(h, wt_fc1 + (size_t)i * 768 * 3072,
                                                  fc1_b + i * MLPD, nullptr, mlp,
                                                  SEQ, MLPD, DIM, 3);
        }
        {   // fc2 + residual -> t (fp32)
            dim3 grid(DIM / 128, (SEQ + 127) / 128);
            gemm_wmma_h<<<grid, 256, GEMM_SMEM>>>(mlp, wt_fc2 + (size_t)i * 3072 * 768,
                                                  fc2_b + i * DIM, t, t,
                                                  SEQ, DIM, MLPD, 0);
        }
    }

    ln_kernel<<<SEQ, 256>>>(t, normf_g, normf_b, h);
    head_kernel<<<BATCH, 256>>>(h, head_w, head_b, out);
}

// round 11
// speedup vs baseline: 3.7672x; 1.1078x over previous
#include <cuda_runtime.h>
#include <cuda_fp16.h>
#include <mma.h>
#include <math.h>
#include <stdint.h>

// ---------------- Model constants ----------------
#define DEPTH   12
#define DIM     768
#define HEADS   12
#define MLPD    3072
#define PP      16
#define GG      14
#define NCLS    1000
#define NTOK    197
#define HD      64
#define BATCH   32
#define SEQ     (BATCH * NTOK)        // 6304
#define PTOK    196
#define PM      (BATCH * PTOK)        // 6272

// ---------------- Scratch (device globals, no allocations) ----------------
__device__ __half g_patches[PM * DIM];        // im2col out (fp16)
__device__ float  g_t      [SEQ * DIM];       // residual stream (fp32)
__device__ __half g_h      [SEQ * DIM];       // LN out (fp16)
__device__ __half g_qkv    [SEQ * 3 * DIM];   // qkv (fp16)
__device__ __half g_o      [SEQ * DIM];       // attn out (fp16)
__device__ __half g_mlp    [SEQ * MLPD];      // MLP hidden (fp16); also reused
                                              // as fp32 temp for patch-embed out

// fp16 weights, contiguous, same layout as inputs.
#define WT_PATCH_SZ  ((long)768*768)
#define WT_QKV_SZ    ((long)DEPTH*768*2304)
#define WT_PROJ_SZ   ((long)DEPTH*768*768)
#define WT_FC1_SZ    ((long)DEPTH*768*3072)
#define WT_FC2_SZ    ((long)DEPTH*3072*768)
#define WT_TOTAL     (WT_PATCH_SZ + WT_QKV_SZ + WT_PROJ_SZ + WT_FC1_SZ + WT_FC2_SZ)
__device__ __half g_wt[WT_TOTAL];

// ---------------- helpers ----------------
__device__ __forceinline__ uint32_t smem_u32(const void* p) {
    uint32_t a;
    asm("{ .reg .u64 t; cvta.to.shared.u64 t, %1; cvt.u32.u64 %0, t; }"
        : "=r"(a) : "l"(p));
    return a;
}
__device__ __forceinline__ void cp16(uint32_t dst, const void* src, int srcbytes) {
    asm volatile("cp.async.cg.shared.global [%0], [%1], 16, %2;"
                 :: "r"(dst), "l"(src), "r"(srcbytes) : "memory");
}
#define CP_COMMIT() asm volatile("cp.async.commit_group;" ::: "memory")
#define CP_WAIT(n)  asm volatile("cp.async.wait_group %0;" :: "n"(n) : "memory")

__device__ __forceinline__ float gelu_exact(float x) {
    return 0.5f * x * (1.0f + erff(x * 0.70710678118654752f));
}

// ---------------- weight conversion fp32 -> fp16 ----------------
__global__ void round_half_kernel(const float* __restrict__ in,
                                  __half* __restrict__ out, long n4) {
    long stride = (long)gridDim.x * blockDim.x;
    for (long i = blockIdx.x * (long)blockDim.x + threadIdx.x; i < n4; i += stride) {
        float4 v = ((const float4*)in)[i];
        ((__half2*)out)[2 * i]     = __floats2half2_rn(v.x, v.y);
        ((__half2*)out)[2 * i + 1] = __floats2half2_rn(v.z, v.w);
    }
}

// ---------------- im2col -> fp16 ----------------
__global__ void im2col_kernel(const float* __restrict__ x, __half* __restrict__ out) {
    int idx = blockIdx.x * blockDim.x + threadIdx.x;
    if (idx >= PM * DIM) return;
    int row = idx / DIM;
    int col = idx - row * DIM;
    int b  = row / PTOK;
    int pt = row - b * PTOK;
    int gi = pt / GG, gj = pt - gi * GG;
    int c  = col >> 8;
    int r  = col & 255;
    int p1 = r >> 4, p2 = r & 15;
    int xi = ((b * 3 + c) * 224 + gi * PP + p1) * 224 + (gj * PP + p2);
    out[idx] = __float2half(x[xi]);
}

// ---------------- assemble: cls + pos (fp32 residual stream) ----------------
__global__ void assemble_kernel(const float* __restrict__ pe,
                                const float* __restrict__ cls,
                                const float* __restrict__ pos,
                                float* __restrict__ t) {
    int idx = blockIdx.x * blockDim.x + threadIdx.x;
    if (idx >= SEQ * DIM) return;
    int row = idx / DIM;
    int c   = idx - row * DIM;
    int b   = row / NTOK;
    int n   = row - b * NTOK;
    float v;
    if (n == 0) v = cls[c];
    else        v = pe[(size_t)(b * PTOK + n - 1) * DIM + c];
    t[idx] = v + pos[n * DIM + c];
}

// ---------------- fp16 WMMA GEMM: C = act(A@W + bias [+res]) ----------------
// A: [M,K] half. W: [K,N] half. N%128==0, K%64==0.
// flags: bit0 = GELU, bit1 = output is __half (else float).
#define BM 128
#define BN 128
#define BK 64
#define AS_H 72            // halves per A smem row (64 + 8 pad); 144 B
#define BS_H 136           // halves per B smem row (128 + 8 pad); 272 B
#define A_TILE_B (BM * AS_H * 2)   // 18432
#define B_TILE_B (BK * BS_H * 2)   // 17408
#define GEMM_SMEM (2 * (A_TILE_B + B_TILE_B))  // 71680

using namespace nvcuda;
typedef wmma::fragment<wmma::matrix_a, 16, 16, 16, __half, wmma::row_major> FragA;
typedef wmma::fragment<wmma::matrix_b, 16, 16, 16, __half, wmma::row_major> FragB;
typedef wmma::fragment<wmma::accumulator, 16, 16, 16, float> FragC;

__device__ __forceinline__ void gemm_issue_chunk_h(
    const __half* __restrict__ A, const __half* __restrict__ W,
    int M, int Nd, int K, int bm0, int bn0, int k0,
    uint32_t aDst, uint32_t bDst, int tid)
{
#pragma unroll
    for (int t = 0; t < 4; t++) {                // A: 128 rows x 8 chunks (16B)
        int id  = tid + t * 256;                 // 0..1023
        int row = id >> 3, c = id & 7;
        int gr  = bm0 + row;
        int ok  = (gr < M);
        const __half* src = A + (ok ? ((size_t)gr * K + k0 + c * 8) : 0);
        cp16(aDst + row * (AS_H * 2) + c * 16, src, ok ? 16 : 0);
    }
#pragma unroll
    for (int t = 0; t < 4; t++) {                // B: 64 rows x 16 chunks (16B)
        int id  = tid + t * 256;
        int row = id >> 4, c = id & 15;
        const __half* src = W + (size_t)(k0 + row) * Nd + bn0 + c * 8;
        cp16(bDst + row * (BS_H * 2) + c * 16, src, 16);
    }
    CP_COMMIT();
}

__global__ void __launch_bounds__(256, 2)
gemm_wmma_h(const __half* __restrict__ A, const __half* __restrict__ W,
            const float* __restrict__ bias, const float* __restrict__ res,
            void* __restrict__ Cv, int M, int Nd, int K, int flags)
{
    extern __shared__ char sm[];
    uint32_t sbase = smem_u32(sm);
    int tid = threadIdx.x, wid = tid >> 5, lane = tid & 31;
    int bn0 = blockIdx.x * BN, bm0 = blockIdx.y * BM;

    const uint32_t ASO[2] = {0u, (uint32_t)A_TILE_B};
    const uint32_t BSO[2] = {(uint32_t)(2 * A_TILE_B),
                             (uint32_t)(2 * A_TILE_B + B_TILE_B)};

    // warp tiling: 2 (m) x 4 (n); warp tile 64x32
    int wm = (wid & 1) * 64;
    int wn = (wid >> 1) * 32;

    FragC acc[4][2];
#pragma unroll
    for (int i = 0; i < 4; i++)
#pragma unroll
        for (int j = 0; j < 2; j++)
            wmma::fill_fragment(acc[i][j], 0.0f);

    int nc = K / BK;
    gemm_issue_chunk_h(A, W, M, Nd, K, bm0, bn0, 0,
                       sbase + ASO[0], sbase + BSO[0], tid);

    for (int ci = 0; ci < nc; ci++) {
        int cur = ci & 1;
        if (ci + 1 < nc) {
            int nxt = cur ^ 1;
            gemm_issue_chunk_h(A, W, M, Nd, K, bm0, bn0, (ci + 1) * BK,
                               sbase + ASO[nxt], sbase + BSO[nxt], tid);
            CP_WAIT(1);
        } else {
            CP_WAIT(0);
        }
        __syncthreads();

        const __half* As = (const __half*)(sm + ASO[cur]);
        const __half* Bs = (const __half*)(sm + BSO[cur]);
#pragma unroll
        for (int kk = 0; kk < 4; kk++) {
            FragB bf[2];
#pragma unroll
            for (int j = 0; j < 2; j++)
                wmma::load_matrix_sync(bf[j], Bs + (kk * 16) * BS_H + wn + j * 16,
                                       BS_H);
#pragma unroll
            for (int i = 0; i < 4; i++) {
                FragA af;
                wmma::load_matrix_sync(af, As + (wm + i * 16) * AS_H + kk * 16,
                                       AS_H);
#pragma unroll
                for (int j = 0; j < 2; j++)
                    wmma::mma_sync(acc[i][j], af, bf[j], acc[i][j]);
            }
        }
        __syncthreads();
    }

    // Epilogue: bounce each 16x16 frag through per-warp smem
    float* patch = (float*)(sm + wid * 1280);   // 16 x 20 floats
    int r  = lane >> 1;
    int cb = (lane & 1) * 8;
    int doGelu  = flags & 1;
    int outHalf = flags & 2;
#pragma unroll
    for (int i = 0; i < 4; i++) {
#pragma unroll
        for (int j = 0; j < 2; j++) {
            wmma::store_matrix_sync(patch, acc[i][j], 20, wmma::mem_row_major);
            __syncwarp();
            int grow = bm0 + wm + i * 16 + r;
            if (grow < M) {
                int gcol = bn0 + wn + j * 16 + cb;
                float4 v0 = *(const float4*)&patch[r * 20 + cb];
                float4 v1 = *(const float4*)&patch[r * 20 + cb + 4];
                float4 b0 = *(const float4*)&bias[gcol];
                float4 b1 = *(const float4*)&bias[gcol + 4];
                v0.x += b0.x; v0.y += b0.y; v0.z += b0.z; v0.w += b0.w;
                v1.x += b1.x; v1.y += b1.y; v1.z += b1.z; v1.w += b1.w;
                if (res) {
                    float4 r0 = *(const float4*)&res[(size_t)grow * Nd + gcol];
                    float4 r1 = *(const float4*)&res[(size_t)grow * Nd + gcol + 4];
                    v0.x += r0.x; v0.y += r0.y; v0.z += r0.z; v0.w += r0.w;
                    v1.x += r1.x; v1.y += r1.y; v1.z += r1.z; v1.w += r1.w;
                }
                if (doGelu) {
                    v0.x = gelu_exact(v0.x); v0.y = gelu_exact(v0.y);
                    v0.z = gelu_exact(v0.z); v0.w = gelu_exact(v0.w);
                    v1.x = gelu_exact(v1.x); v1.y = gelu_exact(v1.y);
                    v1.z = gelu_exact(v1.z); v1.w = gelu_exact(v1.w);
                }
                if (outHalf) {
                    union { uint4 u; __half2 h[4]; } pk;
                    pk.h[0] = __floats2half2_rn(v0.x, v0.y);
                    pk.h[1] = __floats2half2_rn(v0.z, v0.w);
                    pk.h[2] = __floats2half2_rn(v1.x, v1.y);
                    pk.h[3] = __floats2half2_rn(v1.z, v1.w);
                    *(uint4*)&((__half*)Cv)[(size_t)grow * Nd + gcol] = pk.u;
                } else {
                    float* C = (float*)Cv;
                    *(float4*)&C[(size_t)grow * Nd + gcol]     = v0;
                    *(float4*)&C[(size_t)grow * Nd + gcol + 4] = v1;
                }
            }
            __syncwarp();
        }
    }
}

// ---------------- LayerNorm: fp32 in, fp16 out ----------------
__global__ void __launch_bounds__(256)
ln_kernel(const float* __restrict__ in, const float* __restrict__ g,
          const float* __restrict__ b, __half* __restrict__ out) {
    __shared__ float wsum[8], wsum2[8];
    __shared__ float stats[2];
    int row = blockIdx.x, tid = threadIdx.x, wid = tid >> 5, lane = tid & 31;
    const float* x = in + (size_t)row * DIM;
    float v0 = x[tid], v1 = x[tid + 256], v2 = x[tid + 512];
    float s  = v0 + v1 + v2;
    float s2 = v0 * v0 + v1 * v1 + v2 * v2;
#pragma unroll
    for (int off = 16; off > 0; off >>= 1) {
        s  += __shfl_xor_sync(0xffffffffu, s,  off);
        s2 += __shfl_xor_sync(0xffffffffu, s2, off);
    }
    if (lane == 0) { wsum[wid] = s; wsum2[wid] = s2; }
    __syncthreads();
    if (tid == 0) {
        float a = 0.f, c = 0.f;
#pragma unroll
        for (int i = 0; i < 8; i++) { a += wsum[i]; c += wsum2[i]; }
        float m = a * (1.0f / DIM);
        stats[0] = m;
        stats[1] = rsqrtf(c * (1.0f / DIM) - m * m + 1e-6f);
    }
    __syncthreads();
    float m = stats[0], rs = stats[1];
    __half* y = out + (size_t)row * DIM;
    y[tid]       = __float2half((v0 - m) * rs * g[tid]       + b[tid]);
    y[tid + 256] = __float2half((v1 - m) * rs * g[tid + 256] + b[tid + 256]);
    y[tid + 512] = __float2half((v2 - m) * rs * g[tid + 512] + b[tid + 512]);
}

// ---------------- Attention (one block per (b, head)); qkv fp16 ----------------
// smem: K (197 rows, stride 65 fp32) | V (197x64 fp32) | probs 8x200
#define KSTRIDE 65
#define SM_K    0
#define SM_V    12808
#define SM_P    (SM_V + 197 * 64)          // 25416
#define SM_ATTN_FLOATS (SM_P + 8 * 200)    // 27016
#define SM_ATTN_BYTES  (SM_ATTN_FLOATS * 4)

__global__ void __launch_bounds__(256)
attn_kernel(const __half* __restrict__ qkv, const float* __restrict__ mask,
            __half* __restrict__ o) {
    extern __shared__ float smf[];
    float* Ksm = smf + SM_K;
    float* Vsm = smf + SM_V;
    int h = blockIdx.x;
    int b = blockIdx.y;
    int tid = threadIdx.x;
    const __half* base = qkv + (size_t)b * NTOK * (3 * DIM);

    // stage K, V (fp16 -> fp32 smem)
    for (int idx = tid; idx < NTOK * 32; idx += 256) {
        int n  = idx >> 5;
        int d2 = idx & 31;                   // half2 index within 64 dims
        const __half* rowp = base + (size_t)n * (3 * DIM) + h * HD;
        __half2 kv = ((const __half2*)(rowp + DIM))[d2];
        __half2 vv = ((const __half2*)(rowp + 2 * DIM))[d2];
        float2 kf = __half22float2(kv);
        float2 vf = __half22float2(vv);
        Ksm[n * KSTRIDE + 2 * d2]     = kf.x;
        Ksm[n * KSTRIDE + 2 * d2 + 1] = kf.y;
        Vsm[n * 64 + 2 * d2]     = vf.x;
        Vsm[n * 64 + 2 * d2 + 1] = vf.y;
    }
    __syncthreads();

    int wid = tid >> 5, lane = tid & 31;
    float* p = smf + SM_P + wid * 200;

    for (int qi = wid; qi < NTOK; qi += 8) {
        // q in registers (every lane loads the full row; L1-broadcast)
        const __half* qrow = base + (size_t)qi * (3 * DIM) + h * HD;
        float qreg[HD];
#pragma unroll
        for (int d2 = 0; d2 < HD / 2; d2++) {
            float2 qf = __half22float2(((const __half2*)qrow)[d2]);
            qreg[2 * d2]     = qf.x;
            qreg[2 * d2 + 1] = qf.y;
        }

        float s[7];
        float mx = -1e30f;
#pragma unroll
        for (int t = 0; t < 7; t++) {
            int j = t * 32 + lane;
            if (j < NTOK) {
                float acc = 0.0f;
#pragma unroll
                for (int d = 0; d < HD; d++)
                    acc = fmaf(qreg[d], Ksm[j * KSTRIDE + d], acc);
                acc *= 0.125f;
                acc *= mask[qi * NTOK + j];
                s[t] = acc;
                mx = fmaxf(mx, acc);
            } else {
                s[t] = -1e30f;
            }
        }
#pragma unroll
        for (int off = 16; off > 0; off >>= 1)
            mx = fmaxf(mx, __shfl_xor_sync(0xffffffffu, mx, off));

        float sum = 0.0f;
#pragma unroll
        for (int t = 0; t < 7; t++) {
            s[t] = __expf(s[t] - mx);
            sum += s[t];
        }
#pragma unroll
        for (int off = 16; off > 0; off >>= 1)
            sum += __shfl_xor_sync(0xffffffffu, sum, off);
        float inv = 1.0f / sum;
#pragma unroll
        for (int t = 0; t < 7; t++) {
            int j = t * 32 + lane;
            if (j < NTOK) p[j] = s[t] * inv;
        }
        __syncwarp();

        __half* op = o + (size_t)(b * NTOK + qi) * DIM + h * HD;
#pragma unroll
        for (int dd = 0; dd < 2; dd++) {
            int d = lane + dd * 32;
            float acc = 0.0f;
            for (int j = 0; j < NTOK; j++)
                acc = fmaf(p[j], Vsm[j * 64 + d], acc);
            op[d] = __float2half(acc);
        }
        __syncwarp();
    }
}

// ---------------- Head: pooled (fp16 in, fp32 math) ----------------
__global__ void __launch_bounds__(256)
head_kernel(const __half* __restrict__ hf, const float* __restrict__ w,
            const float* __restrict__ hb, float* __restrict__ out) {
    __shared__ float pooled[DIM];
    int b = blockIdx.x;
    int tid = threadIdx.x;
    for (int i = tid; i < DIM; i += 256)
        pooled[i] = __half2float(hf[(size_t)(b * NTOK) * DIM + i]);
    __syncthreads();
    for (int c = tid; c < NCLS; c += 256) {
        float acc = hb[c];
        for (int d = 0; d < DIM; d++)
            acc = fmaf(pooled[d], w[(size_t)d * NCLS + c], acc);
        out[(size_t)b * NCLS + c] = acc;
    }
}

// ---------------- Launch ----------------
extern "C" void kernel_launch(void* const* d_in, const int* in_sizes, int n_in,
                              void* d_out, int out_size) {
    const float* x        = (const float*)d_in[0];
    const float* cp_mask  = (const float*)d_in[1];
    const float* patch_w  = (const float*)d_in[2];
    const float* patch_b  = (const float*)d_in[3];
    const float* cls_tok  = (const float*)d_in[4];
    const float* pos_emb  = (const float*)d_in[5];
    const float* ln1_g    = (const float*)d_in[6];
    const float* ln1_b    = (const float*)d_in[7];
    const float* qkv_w    = (const float*)d_in[8];
    const float* qkv_b    = (const float*)d_in[9];
    const float* proj_w   = (const float*)d_in[10];
    const float* proj_b   = (const float*)d_in[11];
    const float* ln2_g    = (const float*)d_in[12];
    const float* ln2_b    = (const float*)d_in[13];
    const float* fc1_w    = (const float*)d_in[14];
    const float* fc1_b    = (const float*)d_in[15];
    const float* fc2_w    = (const float*)d_in[16];
    const float* fc2_b    = (const float*)d_in[17];
    const float* normf_g  = (const float*)d_in[18];
    const float* normf_b  = (const float*)d_in[19];
    const float* head_w   = (const float*)d_in[20];
    const float* head_b   = (const float*)d_in[21];
    float* out = (float*)d_out;

    __half *pat, *h, *qkv, *o, *mlp, *wt;
    float *t;
    cudaGetSymbolAddress((void**)&pat, g_patches);
    cudaGetSymbolAddress((void**)&t,   g_t);
    cudaGetSymbolAddress((void**)&h,   g_h);
    cudaGetSymbolAddress((void**)&qkv, g_qkv);
    cudaGetSymbolAddress((void**)&o,   g_o);
    cudaGetSymbolAddress((void**)&mlp, g_mlp);
    cudaGetSymbolAddress((void**)&wt,  g_wt);

    cudaFuncSetAttribute(attn_kernel,
                         cudaFuncAttributeMaxDynamicSharedMemorySize, SM_ATTN_BYTES);
    cudaFuncSetAttribute(gemm_wmma_h,
                         cudaFuncAttributeMaxDynamicSharedMemorySize, GEMM_SMEM);

    __half* wt_patch = wt;
    __half* wt_qkv   = wt_patch + WT_PATCH_SZ;
    __half* wt_proj  = wt_qkv   + WT_QKV_SZ;
    __half* wt_fc1   = wt_proj  + WT_PROJ_SZ;
    __half* wt_fc2   = wt_fc1   + WT_FC1_SZ;

    // patch-embed fp32 temp lives in g_mlp's storage (consumed by assemble
    // before fc1 ever writes g_mlp)
    float* patch_out = (float*)mlp;

    // ncu -s 5 -c 1 captures the 6th launch: make it the patch-embed GEMM.
    {   // 1: im2col
        int total = PM * DIM;
        im2col_kernel<<<(total + 255) / 256, 256>>>(x, pat);
    }
    round_half_kernel<<<512, 256>>>(patch_w, wt_patch, WT_PATCH_SZ / 4);   // 2
    round_half_kernel<<<1024, 256>>>(qkv_w,  wt_qkv,  WT_QKV_SZ  / 4);     // 3
    round_half_kernel<<<1024, 256>>>(proj_w, wt_proj, WT_PROJ_SZ / 4);     // 4
    round_half_kernel<<<1024, 256>>>(fc1_w,  wt_fc1,  WT_FC1_SZ  / 4);     // 5
    {   // 6: patch embed GEMM (PROFILED): (6272,768)@(768,768) -> fp32 temp
        dim3 grid(768 / 128, PM / 128);
        gemm_wmma_h<<<grid, 256, GEMM_SMEM>>>(pat, wt_patch, patch_b, nullptr,
                                              patch_out, PM, 768, 768, 0);
    }
    round_half_kernel<<<1024, 256>>>(fc2_w, wt_fc2, WT_FC2_SZ / 4);        // 7
    {   // assemble cls + pos -> t (fp32)
        int total = SEQ * DIM;
        assemble_kernel<<<(total + 255) / 256, 256>>>(patch_out, cls_tok, pos_emb, t);
    }

    for (int i = 0; i < DEPTH; i++) {
        ln_kernel<<<SEQ, 256>>>(t, ln1_g + i * DIM, ln1_b + i * DIM, h);
        {   // QKV: (6304,768)@(768,2304) -> fp16
            dim3 grid((3 * DIM) / 128, (SEQ + 127) / 128);
            gemm_wmma_h<<<grid, 256, GEMM_SMEM>>>(h, wt_qkv + (size_t)i * 768 * 2304,
                                                  qkv_b + i * 3 * DIM, nullptr, qkv,
                                                  SEQ, 3 * DIM, DIM, 2);
        }
        {
            dim3 grid(HEADS, BATCH);
            attn_kernel<<<grid, 256, SM_ATTN_BYTES>>>(qkv, cp_mask, o);
        }
        {   // proj + residual -> t (fp32)
            dim3 grid(DIM / 128, (SEQ + 127) / 128);
            gemm_wmma_h<<<grid, 256, GEMM_SMEM>>>(o, wt_proj + (size_t)i * 768 * 768,
                                                  proj_b + i * DIM, t, t,
                                                  SEQ, DIM, DIM, 0);
        }
        ln_kernel<<<SEQ, 256>>>(t, ln2_g + i * DIM, ln2_b + i * DIM, h);
        {   // fc1 + GELU -> fp16
            dim3 grid(MLPD / 128, (SEQ + 127) / 128);
            gemm_wmma_h<<<grid, 256, GEMM_SMEM>>>(h, wt_fc1 + (size_t)i * 768 * 3072,
                                                  fc1_b + i * MLPD, nullptr, mlp,
                                                  SEQ, MLPD, DIM, 3);
        }
        {   // fc2 + residual -> t (fp32)
            dim3 grid(DIM / 128, (SEQ + 127) / 128);
            gemm_wmma_h<<<grid, 256, GEMM_SMEM>>>(mlp, wt_fc2 + (size_t)i * 3072 * 768,
                                                  fc2_b + i * DIM, t, t,
                                                  SEQ, DIM, MLPD, 0);
        }
    }

    ln_kernel<<<SEQ, 256>>>(t, normf_g, normf_b, h);
    head_kernel<<<BATCH, 256>>>(h, head_w, head_b, out);
}

// round 16
// speedup vs baseline: 3.8243x; 1.0152x over previous
#include <cuda_runtime.h>
#include <cuda_fp16.h>
#include <mma.h>
#include <math.h>
#include <stdint.h>

// ---------------- Model constants ----------------
#define DEPTH   12
#define DIM     768
#define HEADS   12
#define MLPD    3072
#define PP      16
#define GG      14
#define NCLS    1000
#define NTOK    197
#define HD      64
#define BATCH   32
#define SEQ     (BATCH * NTOK)        // 6304
#define PTOK    196
#define PM      (BATCH * PTOK)        // 6272

// ---------------- Scratch (device globals, no allocations) ----------------
__device__ __half g_patches[PM * DIM];        // im2col out (fp16)
__device__ float  g_t      [SEQ * DIM];       // residual stream (fp32)
__device__ __half g_h      [SEQ * DIM];       // LN out (fp16)
__device__ __half g_qkv    [SEQ * 3 * DIM];   // qkv (fp16)
__device__ __half g_o      [SEQ * DIM];       // attn out (fp16)
__device__ __half g_mlp    [SEQ * MLPD];      // MLP hidden (fp16); also reused
                                              // as fp32 temp for patch-embed out

// fp16 weights, contiguous, same layout as inputs.
#define WT_PATCH_SZ  ((long)768*768)
#define WT_QKV_SZ    ((long)DEPTH*768*2304)
#define WT_PROJ_SZ   ((long)DEPTH*768*768)
#define WT_FC1_SZ    ((long)DEPTH*768*3072)
#define WT_FC2_SZ    ((long)DEPTH*3072*768)
#define WT_TOTAL     (WT_PATCH_SZ + WT_QKV_SZ + WT_PROJ_SZ + WT_FC1_SZ + WT_FC2_SZ)
__device__ __half g_wt[WT_TOTAL];

// ---------------- helpers ----------------
__device__ __forceinline__ uint32_t smem_u32(const void* p) {
    uint32_t a;
    asm("{ .reg .u64 t; cvta.to.shared.u64 t, %1; cvt.u32.u64 %0, t; }"
        : "=r"(a) : "l"(p));
    return a;
}
__device__ __forceinline__ void cp16(uint32_t dst, const void* src, int srcbytes) {
    asm volatile("cp.async.cg.shared.global [%0], [%1], 16, %2;"
                 :: "r"(dst), "l"(src), "r"(srcbytes) : "memory");
}
#define CP_COMMIT() asm volatile("cp.async.commit_group;" ::: "memory")
#define CP_WAIT(n)  asm volatile("cp.async.wait_group %0;" :: "n"(n) : "memory")

__device__ __forceinline__ float gelu_exact(float x) {
    return 0.5f * x * (1.0f + erff(x * 0.70710678118654752f));
}

// ---------------- weight conversion fp32 -> fp16 ----------------
__global__ void round_half_kernel(const float* __restrict__ in,
                                  __half* __restrict__ out, long n4) {
    long stride = (long)gridDim.x * blockDim.x;
    for (long i = blockIdx.x * (long)blockDim.x + threadIdx.x; i < n4; i += stride) {
        float4 v = ((const float4*)in)[i];
        ((__half2*)out)[2 * i]     = __floats2half2_rn(v.x, v.y);
        ((__half2*)out)[2 * i + 1] = __floats2half2_rn(v.z, v.w);
    }
}

// ---------------- im2col -> fp16 ----------------
__global__ void im2col_kernel(const float* __restrict__ x, __half* __restrict__ out) {
    int idx = blockIdx.x * blockDim.x + threadIdx.x;
    if (idx >= PM * DIM) return;
    int row = idx / DIM;
    int col = idx - row * DIM;
    int b  = row / PTOK;
    int pt = row - b * PTOK;
    int gi = pt / GG, gj = pt - gi * GG;
    int c  = col >> 8;
    int r  = col & 255;
    int p1 = r >> 4, p2 = r & 15;
    int xi = ((b * 3 + c) * 224 + gi * PP + p1) * 224 + (gj * PP + p2);
    out[idx] = __float2half(x[xi]);
}

// ---------------- assemble: cls + pos (fp32 residual stream) ----------------
__global__ void assemble_kernel(const float* __restrict__ pe,
                                const float* __restrict__ cls,
                                const float* __restrict__ pos,
                                float* __restrict__ t) {
    int idx = blockIdx.x * blockDim.x + threadIdx.x;
    if (idx >= SEQ * DIM) return;
    int row = idx / DIM;
    int c   = idx - row * DIM;
    int b   = row / NTOK;
    int n   = row - b * NTOK;
    float v;
    if (n == 0) v = cls[c];
    else        v = pe[(size_t)(b * PTOK + n - 1) * DIM + c];
    t[idx] = v + pos[n * DIM + c];
}

// ---------------- fp16 WMMA GEMM: C = act(A@W + bias [+res]) ----------------
// A: [M,K] half. W: [K,N] half. N%256==0, K%64==0.
// Block tile 128x256, warp tile 64x64 (8 warps), BK=64, double-buffered.
// flags: bit0 = GELU, bit1 = output is __half (else float).
#define BM 128
#define BN 256
#define BK 64
#define AS_H 72            // halves per A smem row (64 + 8 pad); 144 B
#define BS_H 264           // halves per B smem row (256 + 8 pad); 528 B
#define A_TILE_B (BM * AS_H * 2)   // 18432
#define B_TILE_B (BK * BS_H * 2)   // 33792
#define GEMM_SMEM (2 * (A_TILE_B + B_TILE_B))  // 104448

using namespace nvcuda;
typedef wmma::fragment<wmma::matrix_a, 16, 16, 16, __half, wmma::row_major> FragA;
typedef wmma::fragment<wmma::matrix_b, 16, 16, 16, __half, wmma::row_major> FragB;
typedef wmma::fragment<wmma::accumulator, 16, 16, 16, float> FragC;

__device__ __forceinline__ void gemm_issue_chunk_h(
    const __half* __restrict__ A, const __half* __restrict__ W,
    int M, int Nd, int K, int bm0, int bn0, int k0,
    uint32_t aDst, uint32_t bDst, int tid)
{
#pragma unroll
    for (int t = 0; t < 4; t++) {                // A: 128 rows x 8 chunks (16B)
        int id  = tid + t * 256;                 // 0..1023
        int row = id >> 3, c = id & 7;
        int gr  = bm0 + row;
        int ok  = (gr < M);
        const __half* src = A + (ok ? ((size_t)gr * K + k0 + c * 8) : 0);
        cp16(aDst + row * (AS_H * 2) + c * 16, src, ok ? 16 : 0);
    }
#pragma unroll
    for (int t = 0; t < 8; t++) {                // B: 64 rows x 32 chunks (16B)
        int id  = tid + t * 256;                 // 0..2047
        int row = id >> 5, c = id & 31;
        const __half* src = W + (size_t)(k0 + row) * Nd + bn0 + c * 8;
        cp16(bDst + row * (BS_H * 2) + c * 16, src, 16);
    }
    CP_COMMIT();
}

__global__ void __launch_bounds__(256, 1)
gemm_wmma_h(const __half* __restrict__ A, const __half* __restrict__ W,
            const float* __restrict__ bias, const float* __restrict__ res,
            void* __restrict__ Cv, int M, int Nd, int K, int flags)
{
    extern __shared__ char sm[];
    uint32_t sbase = smem_u32(sm);
    int tid = threadIdx.x, wid = tid >> 5, lane = tid & 31;
    int bn0 = blockIdx.x * BN, bm0 = blockIdx.y * BM;

    const uint32_t ASO[2] = {0u, (uint32_t)A_TILE_B};
    const uint32_t BSO[2] = {(uint32_t)(2 * A_TILE_B),
                             (uint32_t)(2 * A_TILE_B + B_TILE_B)};

    // warp tiling: 2 (m) x 4 (n); warp tile 64x64
    int wm = (wid & 1) * 64;
    int wn = (wid >> 1) * 64;

    FragC acc[4][4];
#pragma unroll
    for (int i = 0; i < 4; i++)
#pragma unroll
        for (int j = 0; j < 4; j++)
            wmma::fill_fragment(acc[i][j], 0.0f);

    int nc = K / BK;
    gemm_issue_chunk_h(A, W, M, Nd, K, bm0, bn0, 0,
                       sbase + ASO[0], sbase + BSO[0], tid);

    for (int ci = 0; ci < nc; ci++) {
        int cur = ci & 1;
        if (ci + 1 < nc) {
            int nxt = cur ^ 1;
            gemm_issue_chunk_h(A, W, M, Nd, K, bm0, bn0, (ci + 1) * BK,
                               sbase + ASO[nxt], sbase + BSO[nxt], tid);
            CP_WAIT(1);
        } else {
            CP_WAIT(0);
        }
        __syncthreads();

        const __half* As = (const __half*)(sm + ASO[cur]);
        const __half* Bs = (const __half*)(sm + BSO[cur]);
#pragma unroll
        for (int kk = 0; kk < 4; kk++) {
            FragB bf[4];
#pragma unroll
            for (int j = 0; j < 4; j++)
                wmma::load_matrix_sync(bf[j], Bs + (kk * 16) * BS_H + wn + j * 16,
                                       BS_H);
#pragma unroll
            for (int i = 0; i < 4; i++) {
                FragA af;
                wmma::load_matrix_sync(af, As + (wm + i * 16) * AS_H + kk * 16,
                                       AS_H);
#pragma unroll
                for (int j = 0; j < 4; j++)
                    wmma::mma_sync(acc[i][j], af, bf[j], acc[i][j]);
            }
        }
        __syncthreads();
    }

    // Epilogue: bounce each 16x16 frag through per-warp smem
    float* patch = (float*)(sm + wid * 1280);   // 16 x 20 floats
    int r  = lane >> 1;
    int cb = (lane & 1) * 8;
    int doGelu  = flags & 1;
    int outHalf = flags & 2;
#pragma unroll
    for (int i = 0; i < 4; i++) {
#pragma unroll
        for (int j = 0; j < 4; j++) {
            wmma::store_matrix_sync(patch, acc[i][j], 20, wmma::mem_row_major);
            __syncwarp();
            int grow = bm0 + wm + i * 16 + r;
            if (grow < M) {
                int gcol = bn0 + wn + j * 16 + cb;
                float4 v0 = *(const float4*)&patch[r * 20 + cb];
                float4 v1 = *(const float4*)&patch[r * 20 + cb + 4];
                float4 b0 = *(const float4*)&bias[gcol];
                float4 b1 = *(const float4*)&bias[gcol + 4];
                v0.x += b0.x; v0.y += b0.y; v0.z += b0.z; v0.w += b0.w;
                v1.x += b1.x; v1.y += b1.y; v1.z += b1.z; v1.w += b1.w;
                if (res) {
                    float4 r0 = *(const float4*)&res[(size_t)grow * Nd + gcol];
                    float4 r1 = *(const float4*)&res[(size_t)grow * Nd + gcol + 4];
                    v0.x += r0.x; v0.y += r0.y; v0.z += r0.z; v0.w += r0.w;
                    v1.x += r1.x; v1.y += r1.y; v1.z += r1.z; v1.w += r1.w;
                }
                if (doGelu) {
                    v0.x = gelu_exact(v0.x); v0.y = gelu_exact(v0.y);
                    v0.z = gelu_exact(v0.z); v0.w = gelu_exact(v0.w);
                    v1.x = gelu_exact(v1.x); v1.y = gelu_exact(v1.y);
                    v1.z = gelu_exact(v1.z); v1.w = gelu_exact(v1.w);
                }
                if (outHalf) {
                    union { uint4 u; __half2 h[4]; } pk;
                    pk.h[0] = __floats2half2_rn(v0.x, v0.y);
                    pk.h[1] = __floats2half2_rn(v0.z, v0.w);
                    pk.h[2] = __floats2half2_rn(v1.x, v1.y);
                    pk.h[3] = __floats2half2_rn(v1.z, v1.w);
                    *(uint4*)&((__half*)Cv)[(size_t)grow * Nd + gcol] = pk.u;
                } else {
                    float* C = (float*)Cv;
                    *(float4*)&C[(size_t)grow * Nd + gcol]     = v0;
                    *(float4*)&C[(size_t)grow * Nd + gcol + 4] = v1;
                }
            }
            __syncwarp();
        }
    }
}

// ---------------- LayerNorm: fp32 in, fp16 out ----------------
__global__ void __launch_bounds__(256)
ln_kernel(const float* __restrict__ in, const float* __restrict__ g,
          const float* __restrict__ b, __half* __restrict__ out) {
    __shared__ float wsum[8], wsum2[8];
    __shared__ float stats[2];
    int row = blockIdx.x, tid = threadIdx.x, wid = tid >> 5, lane = tid & 31;
    const float* x = in + (size_t)row * DIM;
    float v0 = x[tid], v1 = x[tid + 256], v2 = x[tid + 512];
    float s  = v0 + v1 + v2;
    float s2 = v0 * v0 + v1 * v1 + v2 * v2;
#pragma unroll
    for (int off = 16; off > 0; off >>= 1) {
        s  += __shfl_xor_sync(0xffffffffu, s,  off);
        s2 += __shfl_xor_sync(0xffffffffu, s2, off);
    }
    if (lane == 0) { wsum[wid] = s; wsum2[wid] = s2; }
    __syncthreads();
    if (tid == 0) {
        float a = 0.f, c = 0.f;
#pragma unroll
        for (int i = 0; i < 8; i++) { a += wsum[i]; c += wsum2[i]; }
        float m = a * (1.0f / DIM);
        stats[0] = m;
        stats[1] = rsqrtf(c * (1.0f / DIM) - m * m + 1e-6f);
    }
    __syncthreads();
    float m = stats[0], rs = stats[1];
    __half* y = out + (size_t)row * DIM;
    y[tid]       = __float2half((v0 - m) * rs * g[tid]       + b[tid]);
    y[tid + 256] = __float2half((v1 - m) * rs * g[tid + 256] + b[tid + 256]);
    y[tid + 512] = __float2half((v2 - m) * rs * g[tid + 512] + b[tid + 512]);
}

// ---------------- Attention (one block per (b, head)); qkv fp16 ----------------
// smem: K (197 rows, stride 68 fp32, 16B-aligned rows) | V (197x64) | probs 8x200
#define KSTRIDE 68
#define SM_K    0
#define SM_V    (197 * KSTRIDE)            // 13396
#define SM_P    (SM_V + 197 * 64)          // 26004
#define SM_ATTN_FLOATS (SM_P + 8 * 200)    // 27604
#define SM_ATTN_BYTES  (SM_ATTN_FLOATS * 4)

__global__ void __launch_bounds__(256)
attn_kernel(const __half* __restrict__ qkv, const float* __restrict__ mask,
            __half* __restrict__ o) {
    extern __shared__ float smf[];
    float* Ksm = smf + SM_K;
    float* Vsm = smf + SM_V;
    int h = blockIdx.x;
    int b = blockIdx.y;
    int tid = threadIdx.x;
    const __half* base = qkv + (size_t)b * NTOK * (3 * DIM);

    // stage K, V (fp16 -> fp32 smem)
    for (int idx = tid; idx < NTOK * 32; idx += 256) {
        int n  = idx >> 5;
        int d2 = idx & 31;                   // half2 index within 64 dims
        const __half* rowp = base + (size_t)n * (3 * DIM) + h * HD;
        __half2 kv = ((const __half2*)(rowp + DIM))[d2];
        __half2 vv = ((const __half2*)(rowp + 2 * DIM))[d2];
        float2 kf = __half22float2(kv);
        float2 vf = __half22float2(vv);
        Ksm[n * KSTRIDE + 2 * d2]     = kf.x;
        Ksm[n * KSTRIDE + 2 * d2 + 1] = kf.y;
        Vsm[n * 64 + 2 * d2]     = vf.x;
        Vsm[n * 64 + 2 * d2 + 1] = vf.y;
    }
    __syncthreads();

    int wid = tid >> 5, lane = tid & 31;
    float* p = smf + SM_P + wid * 200;

    for (int qi = wid; qi < NTOK; qi += 8) {
        // q in registers (every lane loads the full row; L1-broadcast)
        const __half* qrow = base + (size_t)qi * (3 * DIM) + h * HD;
        float qreg[HD];
#pragma unroll
        for (int d2 = 0; d2 < HD / 2; d2++) {
            float2 qf = __half22float2(((const __half2*)qrow)[d2]);
            qreg[2 * d2]     = qf.x;
            qreg[2 * d2 + 1] = qf.y;
        }

        float s[7];
        float mx = -1e30f;
#pragma unroll
        for (int t = 0; t < 7; t++) {
            int j = t * 32 + lane;
            if (j < NTOK) {
                float acc = 0.0f;
                const float* krow = &Ksm[j * KSTRIDE];
#pragma unroll
                for (int d4 = 0; d4 < HD / 4; d4++) {
                    float4 k4 = *(const float4*)(krow + d4 * 4);
                    acc = fmaf(qreg[4 * d4 + 0], k4.x, acc);
                    acc = fmaf(qreg[4 * d4 + 1], k4.y, acc);
                    acc = fmaf(qreg[4 * d4 + 2], k4.z, acc);
                    acc = fmaf(qreg[4 * d4 + 3], k4.w, acc);
                }
                acc *= 0.125f;
                acc *= mask[qi * NTOK + j];
                s[t] = acc;
                mx = fmaxf(mx, acc);
            } else {
                s[t] = -1e30f;
            }
        }
#pragma unroll
        for (int off = 16; off > 0; off >>= 1)
            mx = fmaxf(mx, __shfl_xor_sync(0xffffffffu, mx, off));

        float sum = 0.0f;
#pragma unroll
        for (int t = 0; t < 7; t++) {
            s[t] = __expf(s[t] - mx);
            sum += s[t];
        }
#pragma unroll
        for (int off = 16; off > 0; off >>= 1)
            sum += __shfl_xor_sync(0xffffffffu, sum, off);
        float inv = 1.0f / sum;
#pragma unroll
        for (int t = 0; t < 7; t++) {
            int j = t * 32 + lane;
            if (j < NTOK) p[j] = s[t] * inv;
        }
        __syncwarp();

        // o = probs @ V : lane owns dims (2*lane, 2*lane+1)
        __half* op = o + (size_t)(b * NTOK + qi) * DIM + h * HD;
        float acc0 = 0.0f, acc1 = 0.0f;
        for (int j = 0; j < NTOK; j++) {
            float pj = p[j];
            float2 v2 = *(const float2*)&Vsm[j * 64 + 2 * lane];
            acc0 = fmaf(pj, v2.x, acc0);
            acc1 = fmaf(pj, v2.y, acc1);
        }
        ((__half2*)op)[lane] = __floats2half2_rn(acc0, acc1);
        __syncwarp();
    }
}

// ---------------- Head: pooled (fp16 in, fp32 math) ----------------
__global__ void __launch_bounds__(256)
head_kernel(const __half* __restrict__ hf, const float* __restrict__ w,
            const float* __restrict__ hb, float* __restrict__ out) {
    __shared__ float pooled[DIM];
    int b = blockIdx.x;
    int tid = threadIdx.x;
    for (int i = tid; i < DIM; i += 256)
        pooled[i] = __half2float(hf[(size_t)(b * NTOK) * DIM + i]);
    __syncthreads();
    for (int c = tid; c < NCLS; c += 256) {
        float acc = hb[c];
        for (int d = 0; d < DIM; d++)
            acc = fmaf(pooled[d], w[(size_t)d * NCLS + c], acc);
        out[(size_t)b * NCLS + c] = acc;
    }
}

// ---------------- Launch ----------------
extern "C" void kernel_launch(void* const* d_in, const int* in_sizes, int n_in,
                              void* d_out, int out_size) {
    const float* x        = (const float*)d_in[0];
    const float* cp_mask  = (const float*)d_in[1];
    const float* patch_w  = (const float*)d_in[2];
    const float* patch_b  = (const float*)d_in[3];
    const float* cls_tok  = (const float*)d_in[4];
    const float* pos_emb  = (const float*)d_in[5];
    const float* ln1_g    = (const float*)d_in[6];
    const float* ln1_b    = (const float*)d_in[7];
    const float* qkv_w    = (const float*)d_in[8];
    const float* qkv_b    = (const float*)d_in[9];
    const float* proj_w   = (const float*)d_in[10];
    const float* proj_b   = (const float*)d_in[11];
    const float* ln2_g    = (const float*)d_in[12];
    const float* ln2_b    = (const float*)d_in[13];
    const float* fc1_w    = (const float*)d_in[14];
    const float* fc1_b    = (const float*)d_in[15];
    const float* fc2_w    = (const float*)d_in[16];
    const float* fc2_b    = (const float*)d_in[17];
    const float* normf_g  = (const float*)d_in[18];
    const float* normf_b  = (const float*)d_in[19];
    const float* head_w   = (const float*)d_in[20];
    const float* head_b   = (const float*)d_in[21];
    float* out = (float*)d_out;

    __half *pat, *h, *qkv, *o, *mlp, *wt;
    float *t;
    cudaGetSymbolAddress((void**)&pat, g_patches);
    cudaGetSymbolAddress((void**)&t,   g_t);
    cudaGetSymbolAddress((void**)&h,   g_h);
    cudaGetSymbolAddress((void**)&qkv, g_qkv);
    cudaGetSymbolAddress((void**)&o,   g_o);
    cudaGetSymbolAddress((void**)&mlp, g_mlp);
    cudaGetSymbolAddress((void**)&wt,  g_wt);

    cudaFuncSetAttribute(attn_kernel,
                         cudaFuncAttributeMaxDynamicSharedMemorySize, SM_ATTN_BYTES);
    cudaFuncSetAttribute(gemm_wmma_h,
                         cudaFuncAttributeMaxDynamicSharedMemorySize, GEMM_SMEM);

    __half* wt_patch = wt;
    __half* wt_qkv   = wt_patch + WT_PATCH_SZ;
    __half* wt_proj  = wt_qkv   + WT_QKV_SZ;
    __half* wt_fc1   = wt_proj  + WT_PROJ_SZ;
    __half* wt_fc2   = wt_fc1   + WT_FC1_SZ;

    // patch-embed fp32 temp lives in g_mlp's storage (consumed by assemble
    // before fc1 ever writes g_mlp)
    float* patch_out = (float*)mlp;

    {   // im2col
        int total = PM * DIM;
        im2col_kernel<<<(total + 255) / 256, 256>>>(x, pat);
    }
    round_half_kernel<<<512, 256>>>(patch_w, wt_patch, WT_PATCH_SZ / 4);
    round_half_kernel<<<1024, 256>>>(qkv_w,  wt_qkv,  WT_QKV_SZ  / 4);
    round_half_kernel<<<1024, 256>>>(proj_w, wt_proj, WT_PROJ_SZ / 4);
    round_half_kernel<<<1024, 256>>>(fc1_w,  wt_fc1,  WT_FC1_SZ  / 4);
    {   // patch embed GEMM: (6272,768)@(768,768) -> fp32 temp
        dim3 grid(768 / BN, (PM + BM - 1) / BM);
        gemm_wmma_h<<<grid, 256, GEMM_SMEM>>>(pat, wt_patch, patch_b, nullptr,
                                              patch_out, PM, 768, 768, 0);
    }
    round_half_kernel<<<1024, 256>>>(fc2_w, wt_fc2, WT_FC2_SZ / 4);
    {   // assemble cls + pos -> t (fp32)
        int total = SEQ * DIM;
        assemble_kernel<<<(total + 255) / 256, 256>>>(patch_out, cls_tok, pos_emb, t);
    }

    for (int i = 0; i < DEPTH; i++) {
        ln_kernel<<<SEQ, 256>>>(t, ln1_g + i * DIM, ln1_b + i * DIM, h);
        {   // QKV: (6304,768)@(768,2304) -> fp16
            dim3 grid((3 * DIM) / BN, (SEQ + BM - 1) / BM);
            gemm_wmma_h<<<grid, 256, GEMM_SMEM>>>(h, wt_qkv + (size_t)i * 768 * 2304,
                                                  qkv_b + i * 3 * DIM, nullptr, qkv,
                                                  SEQ, 3 * DIM, DIM, 2);
        }
        {
            dim3 grid(HEADS, BATCH);
            attn_kernel<<<grid, 256, SM_ATTN_BYTES>>>(qkv, cp_mask, o);
        }
        {   // proj + residual -> t (fp32)
            dim3 grid(DIM / BN, (SEQ + BM - 1) / BM);
            gemm_wmma_h<<<grid, 256, GEMM_SMEM>>>(o, wt_proj + (size_t)i * 768 * 768,
                                                  proj_b + i * DIM, t, t,
                                                  SEQ, DIM, DIM, 0);
        }
        ln_kernel<<<SEQ, 256>>>(t, ln2_g + i * DIM, ln2_b + i * DIM, h);
        {   // fc1 + GELU -> fp16
            dim3 grid(MLPD / BN, (SEQ + BM - 1) / BM);
            gemm_wmma_h<<<grid, 256, GEMM_SMEM>>>(h, wt_fc1 + (size_t)i * 768 * 3072,
                                                  fc1_b + i * MLPD, nullptr, mlp,
                                                  SEQ, MLPD, DIM, 3);
        }
        {   // fc2 + residual -> t (fp32)
            dim3 grid(DIM / BN, (SEQ + BM - 1) / BM);
            gemm_wmma_h<<<grid, 256, GEMM_SMEM>>>(mlp, wt_fc2 + (size_t)i * 3072 * 768,
                                                  fc2_b + i * DIM, t, t,
                                                  SEQ, DIM, MLPD, 0);
        }
    }

    ln_kernel<<<SEQ, 256>>>(t, normf_g, normf_b, h);
    head_kernel<<<BATCH, 256>>>(h, head_w, head_b, out);
}

// round 17
// speedup vs baseline: 3.8806x; 1.0147x over previous
#include <cuda_runtime.h>
#include <cuda_fp16.h>
#include <mma.h>
#include <math.h>
#include <stdint.h>

// ---------------- Model constants ----------------
#define DEPTH   12
#define DIM     768
#define HEADS   12
#define MLPD    3072
#define PP      16
#define GG      14
#define NCLS    1000
#define NTOK    197
#define HD      64
#define BATCH   32
#define SEQ     (BATCH * NTOK)        // 6304
#define PTOK    196
#define PM      (BATCH * PTOK)        // 6272

// ---------------- Scratch (device globals, no allocations) ----------------
__device__ __half g_patches[PM * DIM];        // im2col out (fp16)
__device__ float  g_t      [SEQ * DIM];       // residual stream (fp32)
__device__ __half g_h      [SEQ * DIM];       // LN out (fp16)
__device__ __half g_qkv    [SEQ * 3 * DIM];   // qkv (fp16)
__device__ __half g_o      [SEQ * DIM];       // attn out (fp16)
__device__ __half g_mlp    [SEQ * MLPD];      // MLP hidden (fp16); also reused
                                              // as fp32 temp for patch-embed out

// fp16 weights, contiguous, same layout as inputs.
#define WT_PATCH_SZ  ((long)768*768)
#define WT_QKV_SZ    ((long)DEPTH*768*2304)
#define WT_PROJ_SZ   ((long)DEPTH*768*768)
#define WT_FC1_SZ    ((long)DEPTH*768*3072)
#define WT_FC2_SZ    ((long)DEPTH*3072*768)
#define WT_TOTAL     (WT_PATCH_SZ + WT_QKV_SZ + WT_PROJ_SZ + WT_FC1_SZ + WT_FC2_SZ)
__device__ __half g_wt[WT_TOTAL];

// ---------------- helpers ----------------
__device__ __forceinline__ uint32_t smem_u32(const void* p) {
    uint32_t a;
    asm("{ .reg .u64 t; cvta.to.shared.u64 t, %1; cvt.u32.u64 %0, t; }"
        : "=r"(a) : "l"(p));
    return a;
}
__device__ __forceinline__ void cp16(uint32_t dst, const void* src, int srcbytes) {
    asm volatile("cp.async.cg.shared.global [%0], [%1], 16, %2;"
                 :: "r"(dst), "l"(src), "r"(srcbytes) : "memory");
}
#define CP_COMMIT() asm volatile("cp.async.commit_group;" ::: "memory")
#define CP_WAIT(n)  asm volatile("cp.async.wait_group %0;" :: "n"(n) : "memory")

__device__ __forceinline__ float gelu_exact(float x) {
    return 0.5f * x * (1.0f + erff(x * 0.70710678118654752f));
}

// ---------------- weight conversion fp32 -> fp16 ----------------
__global__ void round_half_kernel(const float* __restrict__ in,
                                  __half* __restrict__ out, long n4) {
    long stride = (long)gridDim.x * blockDim.x;
    for (long i = blockIdx.x * (long)blockDim.x + threadIdx.x; i < n4; i += stride) {
        float4 v = ((const float4*)in)[i];
        ((__half2*)out)[2 * i]     = __floats2half2_rn(v.x, v.y);
        ((__half2*)out)[2 * i + 1] = __floats2half2_rn(v.z, v.w);
    }
}

// ---------------- im2col -> fp16 ----------------
__global__ void im2col_kernel(const float* __restrict__ x, __half* __restrict__ out) {
    int idx = blockIdx.x * blockDim.x + threadIdx.x;
    if (idx >= PM * DIM) return;
    int row = idx / DIM;
    int col = idx - row * DIM;
    int b  = row / PTOK;
    int pt = row - b * PTOK;
    int gi = pt / GG, gj = pt - gi * GG;
    int c  = col >> 8;
    int r  = col & 255;
    int p1 = r >> 4, p2 = r & 15;
    int xi = ((b * 3 + c) * 224 + gi * PP + p1) * 224 + (gj * PP + p2);
    out[idx] = __float2half(x[xi]);
}

// ---------------- assemble: cls + pos (fp32 residual stream) ----------------
__global__ void assemble_kernel(const float* __restrict__ pe,
                                const float* __restrict__ cls,
                                const float* __restrict__ pos,
                                float* __restrict__ t) {
    int idx = blockIdx.x * blockDim.x + threadIdx.x;
    if (idx >= SEQ * DIM) return;
    int row = idx / DIM;
    int c   = idx - row * DIM;
    int b   = row / NTOK;
    int n   = row - b * NTOK;
    float v;
    if (n == 0) v = cls[c];
    else        v = pe[(size_t)(b * PTOK + n - 1) * DIM + c];
    t[idx] = v + pos[n * DIM + c];
}

// ---------------- fp16 WMMA GEMM: C = act(A@W + bias [+res]) ----------------
// A: [M,K] half. W: [K,N] half. N%256==0, K%64==0.
// Block tile 128x256, warp tile 64x64 (8 warps), BK=64, 3-stage cp.async.
// flags: bit0 = GELU, bit1 = output is __half (else float).
#define BM 128
#define BN 256
#define BK 64
#define AS_H 72            // halves per A smem row (64 + 8 pad); 144 B
#define BS_H 264           // halves per B smem row (256 + 8 pad); 528 B
#define A_TILE_B (BM * AS_H * 2)   // 18432
#define B_TILE_B (BK * BS_H * 2)   // 33792
#define STAGE_B  (A_TILE_B + B_TILE_B)         // 52224
#define NSTAGE   3
#define GEMM_SMEM (NSTAGE * STAGE_B)           // 156672

using namespace nvcuda;
typedef wmma::fragment<wmma::matrix_a, 16, 16, 16, __half, wmma::row_major> FragA;
typedef wmma::fragment<wmma::matrix_b, 16, 16, 16, __half, wmma::row_major> FragB;
typedef wmma::fragment<wmma::accumulator, 16, 16, 16, float> FragC;

__device__ __forceinline__ void gemm_issue_chunk_h(
    const __half* __restrict__ A, const __half* __restrict__ W,
    int M, int Nd, int K, int bm0, int bn0, int k0,
    uint32_t aDst, uint32_t bDst, int tid)
{
#pragma unroll
    for (int t = 0; t < 4; t++) {                // A: 128 rows x 8 chunks (16B)
        int id  = tid + t * 256;                 // 0..1023
        int row = id >> 3, c = id & 7;
        int gr  = bm0 + row;
        int ok  = (gr < M);
        const __half* src = A + (ok ? ((size_t)gr * K + k0 + c * 8) : 0);
        cp16(aDst + row * (AS_H * 2) + c * 16, src, ok ? 16 : 0);
    }
#pragma unroll
    for (int t = 0; t < 8; t++) {                // B: 64 rows x 32 chunks (16B)
        int id  = tid + t * 256;                 // 0..2047
        int row = id >> 5, c = id & 31;
        const __half* src = W + (size_t)(k0 + row) * Nd + bn0 + c * 8;
        cp16(bDst + row * (BS_H * 2) + c * 16, src, 16);
    }
    CP_COMMIT();
}

__global__ void __launch_bounds__(256, 1)
gemm_wmma_h(const __half* __restrict__ A, const __half* __restrict__ W,
            const float* __restrict__ bias, const float* __restrict__ res,
            void* __restrict__ Cv, int M, int Nd, int K, int flags)
{
    extern __shared__ char sm[];
    uint32_t sbase = smem_u32(sm);
    int tid = threadIdx.x, wid = tid >> 5, lane = tid & 31;
    int bn0 = blockIdx.x * BN, bm0 = blockIdx.y * BM;

    // warp tiling: 2 (m) x 4 (n); warp tile 64x64
    int wm = (wid & 1) * 64;
    int wn = (wid >> 1) * 64;

    FragC acc[4][4];
#pragma unroll
    for (int i = 0; i < 4; i++)
#pragma unroll
        for (int j = 0; j < 4; j++)
            wmma::fill_fragment(acc[i][j], 0.0f);

    int nc = K / BK;
    // Prologue: stage chunks 0 and 1
    gemm_issue_chunk_h(A, W, M, Nd, K, bm0, bn0, 0,
                       sbase, sbase + A_TILE_B, tid);
    if (nc > 1)
        gemm_issue_chunk_h(A, W, M, Nd, K, bm0, bn0, BK,
                           sbase + STAGE_B, sbase + STAGE_B + A_TILE_B, tid);

    for (int ci = 0; ci < nc; ci++) {
        int cur = ci % NSTAGE;
        if (ci + 1 < nc) CP_WAIT(1);   // chunk ci landed; ci+1 still streaming
        else             CP_WAIT(0);
        __syncthreads();               // all warps done with chunk ci-1's buffer

        // Prefetch chunk ci+2 into the buffer chunk ci-1 just vacated
        if (ci + 2 < nc) {
            int nb = (ci + 2) % NSTAGE;
            gemm_issue_chunk_h(A, W, M, Nd, K, bm0, bn0, (ci + 2) * BK,
                               sbase + nb * STAGE_B,
                               sbase + nb * STAGE_B + A_TILE_B, tid);
        }

        const __half* As = (const __half*)(sm + cur * STAGE_B);
        const __half* Bs = (const __half*)(sm + cur * STAGE_B + A_TILE_B);
#pragma unroll
        for (int kk = 0; kk < 4; kk++) {
            FragB bf[4];
#pragma unroll
            for (int j = 0; j < 4; j++)
                wmma::load_matrix_sync(bf[j], Bs + (kk * 16) * BS_H + wn + j * 16,
                                       BS_H);
#pragma unroll
            for (int i = 0; i < 4; i++) {
                FragA af;
                wmma::load_matrix_sync(af, As + (wm + i * 16) * AS_H + kk * 16,
                                       AS_H);
#pragma unroll
                for (int j = 0; j < 4; j++)
                    wmma::mma_sync(acc[i][j], af, bf[j], acc[i][j]);
            }
        }
    }
    __syncthreads();   // before epilogue reuses stage-0 smem

    // Epilogue: bounce each 16x16 frag through per-warp smem
    float* patch = (float*)(sm + wid * 1280);   // 16 x 20 floats
    int r  = lane >> 1;
    int cb = (lane & 1) * 8;
    int doGelu  = flags & 1;
    int outHalf = flags & 2;
#pragma unroll
    for (int i = 0; i < 4; i++) {
#pragma unroll
        for (int j = 0; j < 4; j++) {
            wmma::store_matrix_sync(patch, acc[i][j], 20, wmma::mem_row_major);
            __syncwarp();
            int grow = bm0 + wm + i * 16 + r;
            if (grow < M) {
                int gcol = bn0 + wn + j * 16 + cb;
                float4 v0 = *(const float4*)&patch[r * 20 + cb];
                float4 v1 = *(const float4*)&patch[r * 20 + cb + 4];
                float4 b0 = *(const float4*)&bias[gcol];
                float4 b1 = *(const float4*)&bias[gcol + 4];
                v0.x += b0.x; v0.y += b0.y; v0.z += b0.z; v0.w += b0.w;
                v1.x += b1.x; v1.y += b1.y; v1.z += b1.z; v1.w += b1.w;
                if (res) {
                    float4 r0 = *(const float4*)&res[(size_t)grow * Nd + gcol];
                    float4 r1 = *(const float4*)&res[(size_t)grow * Nd + gcol + 4];
                    v0.x += r0.x; v0.y += r0.y; v0.z += r0.z; v0.w += r0.w;
                    v1.x += r1.x; v1.y += r1.y; v1.z += r1.z; v1.w += r1.w;
                }
                if (doGelu) {
                    v0.x = gelu_exact(v0.x); v0.y = gelu_exact(v0.y);
                    v0.z = gelu_exact(v0.z); v0.w = gelu_exact(v0.w);
                    v1.x = gelu_exact(v1.x); v1.y = gelu_exact(v1.y);
                    v1.z = gelu_exact(v1.z); v1.w = gelu_exact(v1.w);
                }
                if (outHalf) {
                    union { uint4 u; __half2 h[4]; } pk;
                    pk.h[0] = __floats2half2_rn(v0.x, v0.y);
                    pk.h[1] = __floats2half2_rn(v0.z, v0.w);
                    pk.h[2] = __floats2half2_rn(v1.x, v1.y);
                    pk.h[3] = __floats2half2_rn(v1.z, v1.w);
                    *(uint4*)&((__half*)Cv)[(size_t)grow * Nd + gcol] = pk.u;
                } else {
                    float* C = (float*)Cv;
                    *(float4*)&C[(size_t)grow * Nd + gcol]     = v0;
                    *(float4*)&C[(size_t)grow * Nd + gcol + 4] = v1;
                }
            }
            __syncwarp();
        }
    }
}

// ---------------- LayerNorm: fp32 in, fp16 out ----------------
__global__ void __launch_bounds__(256)
ln_kernel(const float* __restrict__ in, const float* __restrict__ g,
          const float* __restrict__ b, __half* __restrict__ out) {
    __shared__ float wsum[8], wsum2[8];
    __shared__ float stats[2];
    int row = blockIdx.x, tid = threadIdx.x, wid = tid >> 5, lane = tid & 31;
    const float* x = in + (size_t)row * DIM;
    float v0 = x[tid], v1 = x[tid + 256], v2 = x[tid + 512];
    float s  = v0 + v1 + v2;
    float s2 = v0 * v0 + v1 * v1 + v2 * v2;
#pragma unroll
    for (int off = 16; off > 0; off >>= 1) {
        s  += __shfl_xor_sync(0xffffffffu, s,  off);
        s2 += __shfl_xor_sync(0xffffffffu, s2, off);
    }
    if (lane == 0) { wsum[wid] = s; wsum2[wid] = s2; }
    __syncthreads();
    if (tid == 0) {
        float a = 0.f, c = 0.f;
#pragma unroll
        for (int i = 0; i < 8; i++) { a += wsum[i]; c += wsum2[i]; }
        float m = a * (1.0f / DIM);
        stats[0] = m;
        stats[1] = rsqrtf(c * (1.0f / DIM) - m * m + 1e-6f);
    }
    __syncthreads();
    float m = stats[0], rs = stats[1];
    __half* y = out + (size_t)row * DIM;
    y[tid]       = __float2half((v0 - m) * rs * g[tid]       + b[tid]);
    y[tid + 256] = __float2half((v1 - m) * rs * g[tid + 256] + b[tid + 256]);
    y[tid + 512] = __float2half((v2 - m) * rs * g[tid + 512] + b[tid + 512]);
}

// ---------------- Attention (one block per (b, head)); qkv fp16 ----------------
// smem: K (197 rows, stride 68 fp32, 16B-aligned rows) | V (197x64) | probs 8x200
#define KSTRIDE 68
#define SM_K    0
#define SM_V    (197 * KSTRIDE)            // 13396
#define SM_P    (SM_V + 197 * 64)          // 26004
#define SM_ATTN_FLOATS (SM_P + 8 * 200)    // 27604
#define SM_ATTN_BYTES  (SM_ATTN_FLOATS * 4)

__global__ void __launch_bounds__(256)
attn_kernel(const __half* __restrict__ qkv, const float* __restrict__ mask,
            __half* __restrict__ o) {
    extern __shared__ float smf[];
    float* Ksm = smf + SM_K;
    float* Vsm = smf + SM_V;
    int h = blockIdx.x;
    int b = blockIdx.y;
    int tid = threadIdx.x;
    const __half* base = qkv + (size_t)b * NTOK * (3 * DIM);

    // stage K, V (fp16 -> fp32 smem)
    for (int idx = tid; idx < NTOK * 32; idx += 256) {
        int n  = idx >> 5;
        int d2 = idx & 31;                   // half2 index within 64 dims
        const __half* rowp = base + (size_t)n * (3 * DIM) + h * HD;
        __half2 kv = ((const __half2*)(rowp + DIM))[d2];
        __half2 vv = ((const __half2*)(rowp + 2 * DIM))[d2];
        float2 kf = __half22float2(kv);
        float2 vf = __half22float2(vv);
        Ksm[n * KSTRIDE + 2 * d2]     = kf.x;
        Ksm[n * KSTRIDE + 2 * d2 + 1] = kf.y;
        Vsm[n * 64 + 2 * d2]     = vf.x;
        Vsm[n * 64 + 2 * d2 + 1] = vf.y;
    }
    __syncthreads();

    int wid = tid >> 5, lane = tid & 31;
    float* p = smf + SM_P + wid * 200;

    for (int qi = wid; qi < NTOK; qi += 8) {
        // q in registers (every lane loads the full row; L1-broadcast)
        const __half* qrow = base + (size_t)qi * (3 * DIM) + h * HD;
        float qreg[HD];
#pragma unroll
        for (int d2 = 0; d2 < HD / 2; d2++) {
            float2 qf = __half22float2(((const __half2*)qrow)[d2]);
            qreg[2 * d2]     = qf.x;
            qreg[2 * d2 + 1] = qf.y;
        }

        float s[7];
        float mx = -1e30f;
#pragma unroll
        for (int t = 0; t < 7; t++) {
            int j = t * 32 + lane;
            if (j < NTOK) {
                float acc = 0.0f;
                const float* krow = &Ksm[j * KSTRIDE];
#pragma unroll
                for (int d4 = 0; d4 < HD / 4; d4++) {
                    float4 k4 = *(const float4*)(krow + d4 * 4);
                    acc = fmaf(qreg[4 * d4 + 0], k4.x, acc);
                    acc = fmaf(qreg[4 * d4 + 1], k4.y, acc);
                    acc = fmaf(qreg[4 * d4 + 2], k4.z, acc);
                    acc = fmaf(qreg[4 * d4 + 3], k4.w, acc);
                }
                acc *= 0.125f;
                acc *= mask[qi * NTOK + j];
                s[t] = acc;
                mx = fmaxf(mx, acc);
            } else {
                s[t] = -1e30f;
            }
        }
#pragma unroll
        for (int off = 16; off > 0; off >>= 1)
            mx = fmaxf(mx, __shfl_xor_sync(0xffffffffu, mx, off));

        float sum = 0.0f;
#pragma unroll
        for (int t = 0; t < 7; t++) {
            s[t] = __expf(s[t] - mx);
            sum += s[t];
        }
#pragma unroll
        for (int off = 16; off > 0; off >>= 1)
            sum += __shfl_xor_sync(0xffffffffu, sum, off);
        float inv = 1.0f / sum;
#pragma unroll
        for (int t = 0; t < 7; t++) {
            int j = t * 32 + lane;
            if (j < NTOK) p[j] = s[t] * inv;
        }
        __syncwarp();

        // o = probs @ V : lane owns dims (2*lane, 2*lane+1)
        __half* op = o + (size_t)(b * NTOK + qi) * DIM + h * HD;
        float acc0 = 0.0f, acc1 = 0.0f;
        for (int j = 0; j < NTOK; j++) {
            float pj = p[j];
            float2 v2 = *(const float2*)&Vsm[j * 64 + 2 * lane];
            acc0 = fmaf(pj, v2.x, acc0);
            acc1 = fmaf(pj, v2.y, acc1);
        }
        ((__half2*)op)[lane] = __floats2half2_rn(acc0, acc1);
        __syncwarp();
    }
}

// ---------------- Head: pooled (fp16 in, fp32 math) ----------------
__global__ void __launch_bounds__(256)
head_kernel(const __half* __restrict__ hf, const float* __restrict__ w,
            const float* __restrict__ hb, float* __restrict__ out) {
    __shared__ float pooled[DIM];
    int b = blockIdx.x;
    int tid = threadIdx.x;
    for (int i = tid; i < DIM; i += 256)
        pooled[i] = __half2float(hf[(size_t)(b * NTOK) * DIM + i]);
    __syncthreads();
    for (int c = tid; c < NCLS; c += 256) {
        float acc = hb[c];
        for (int d = 0; d < DIM; d++)
            acc = fmaf(pooled[d], w[(size_t)d * NCLS + c], acc);
        out[(size_t)b * NCLS + c] = acc;
    }
}

// ---------------- Launch ----------------
extern "C" void kernel_launch(void* const* d_in, const int* in_sizes, int n_in,
                              void* d_out, int out_size) {
    const float* x        = (const float*)d_in[0];
    const float* cp_mask  = (const float*)d_in[1];
    const float* patch_w  = (const float*)d_in[2];
    const float* patch_b  = (const float*)d_in[3];
    const float* cls_tok  = (const float*)d_in[4];
    const float* pos_emb  = (const float*)d_in[5];
    const float* ln1_g    = (const float*)d_in[6];
    const float* ln1_b    = (const float*)d_in[7];
    const float* qkv_w    = (const float*)d_in[8];
    const float* qkv_b    = (const float*)d_in[9];
    const float* proj_w   = (const float*)d_in[10];
    const float* proj_b   = (const float*)d_in[11];
    const float* ln2_g    = (const float*)d_in[12];
    const float* ln2_b    = (const float*)d_in[13];
    const float* fc1_w    = (const float*)d_in[14];
    const float* fc1_b    = (const float*)d_in[15];
    const float* fc2_w    = (const float*)d_in[16];
    const float* fc2_b    = (const float*)d_in[17];
    const float* normf_g  = (const float*)d_in[18];
    const float* normf_b  = (const float*)d_in[19];
    const float* head_w   = (const float*)d_in[20];
    const float* head_b   = (const float*)d_in[21];
    float* out = (float*)d_out;

    __half *pat, *h, *qkv, *o, *mlp, *wt;
    float *t;
    cudaGetSymbolAddress((void**)&pat, g_patches);
    cudaGetSymbolAddress((void**)&t,   g_t);
    cudaGetSymbolAddress((void**)&h,   g_h);
    cudaGetSymbolAddress((void**)&qkv, g_qkv);
    cudaGetSymbolAddress((void**)&o,   g_o);
    cudaGetSymbolAddress((void**)&mlp, g_mlp);
    cudaGetSymbolAddress((void**)&wt,  g_wt);

    cudaFuncSetAttribute(attn_kernel,
                         cudaFuncAttributeMaxDynamicSharedMemorySize, SM_ATTN_BYTES);
    cudaFuncSetAttribute(gemm_wmma_h,
                         cudaFuncAttributeMaxDynamicSharedMemorySize, GEMM_SMEM);

    __half* wt_patch = wt;
    __half* wt_qkv   = wt_patch + WT_PATCH_SZ;
    __half* wt_proj  = wt_qkv   + WT_QKV_SZ;
    __half* wt_fc1   = wt_proj  + WT_PROJ_SZ;
    __half* wt_fc2   = wt_fc1   + WT_FC1_SZ;

    // patch-embed fp32 temp lives in g_mlp's storage (consumed by assemble
    // before fc1 ever writes g_mlp)
    float* patch_out = (float*)mlp;

    {   // im2col
        int total = PM * DIM;
        im2col_kernel<<<(total + 255) / 256, 256>>>(x, pat);
    }
    round_half_kernel<<<512, 256>>>(patch_w, wt_patch, WT_PATCH_SZ / 4);
    round_half_kernel<<<1024, 256>>>(qkv_w,  wt_qkv,  WT_QKV_SZ  / 4);
    round_half_kernel<<<1024, 256>>>(proj_w, wt_proj, WT_PROJ_SZ / 4);
    round_half_kernel<<<1024, 256>>>(fc1_w,  wt_fc1,  WT_FC1_SZ  / 4);
    {   // patch embed GEMM: (6272,768)@(768,768) -> fp32 temp
        dim3 grid(768 / BN, (PM + BM - 1) / BM);
        gemm_wmma_h<<<grid, 256, GEMM_SMEM>>>(pat, wt_patch, patch_b, nullptr,
                                              patch_out, PM, 768, 768, 0);
    }
    round_half_kernel<<<1024, 256>>>(fc2_w, wt_fc2, WT_FC2_SZ / 4);
    {   // assemble cls + pos -> t (fp32)
        int total = SEQ * DIM;
        assemble_kernel<<<(total + 255) / 256, 256>>>(patch_out, cls_tok, pos_emb, t);
    }

    for (int i = 0; i < DEPTH; i++) {
        ln_kernel<<<SEQ, 256>>>(t, ln1_g + i * DIM, ln1_b + i * DIM, h);
        {   // QKV: (6304,768)@(768,2304) -> fp16
            dim3 grid((3 * DIM) / BN, (SEQ + BM - 1) / BM);
            gemm_wmma_h<<<grid, 256, GEMM_SMEM>>>(h, wt_qkv + (size_t)i * 768 * 2304,
                                                  qkv_b + i * 3 * DIM, nullptr, qkv,
                                                  SEQ, 3 * DIM, DIM, 2);
        }
        {
            dim3 grid(HEADS, BATCH);
            attn_kernel<<<grid, 256, SM_ATTN_BYTES>>>(qkv, cp_mask, o);
        }
        {   // proj + residual -> t (fp32)
            dim3 grid(DIM / BN, (SEQ + BM - 1) / BM);
            gemm_wmma_h<<<grid, 256, GEMM_SMEM>>>(o, wt_proj + (size_t)i * 768 * 768,
                                                  proj_b + i * DIM, t, t,
                                                  SEQ, DIM, DIM, 0);
        }
        ln_kernel<<<SEQ, 256>>>(t, ln2_g + i * DIM, ln2_b + i * DIM, h);
        {   // fc1 + GELU -> fp16
            dim3 grid(MLPD / BN, (SEQ + BM - 1) / BM);
            gemm_wmma_h<<<grid, 256, GEMM_SMEM>>>(h, wt_fc1 + (size_t)i * 768 * 3072,
                                                  fc1_b + i * MLPD, nullptr, mlp,
                                                  SEQ, MLPD, DIM, 3);
        }
        {   // fc2 + residual -> t (fp32)
            dim3 grid(DIM / BN, (SEQ + BM - 1) / BM);
            gemm_wmma_h<<<grid, 256, GEMM_SMEM>>>(mlp, wt_fc2 + (size_t)i * 3072 * 768,
                                                  fc2_b + i * DIM, t, t,
                                                  SEQ, DIM, MLPD, 0);
        }
    }

    ln_kernel<<<SEQ, 256>>>(t, normf_g, normf_b, h);
    head_kernel<<<BATCH, 256>>>(h, head_w, head_b, out);
}